// round 12
// baseline (speedup 1.0000x reference)
#include <cuda_runtime.h>
#include <cuda_fp16.h>
#include <math.h>
#include <stdint.h>

// Problem constants
#define Bv   2048
#define Sv   64
#define Fv   16
#define Hv   512
#define H4   2048
#define Ev   8
#define HHv  256
#define HOR  8
#define BH   (Bv*Hv)

// ======================= portable tensor-op helpers (sm_80+) =======================
__device__ __forceinline__ uint32_t smem_to_u32(const void* p) {
    uint32_t a;
    asm("{ .reg .u64 t; cvta.to.shared.u64 t, %1; cvt.u32.u64 %0, t; }" : "=r"(a) : "l"(p));
    return a;
}
__device__ __forceinline__ void mma16816(float* c, const uint32_t* a, const uint32_t* b) {
    asm volatile("mma.sync.aligned.m16n8k16.row.col.f32.f16.f16.f32 "
        "{%0,%1,%2,%3}, {%4,%5,%6,%7}, {%8,%9}, {%0,%1,%2,%3};"
        : "+f"(c[0]), "+f"(c[1]), "+f"(c[2]), "+f"(c[3])
        : "r"(a[0]), "r"(a[1]), "r"(a[2]), "r"(a[3]), "r"(b[0]), "r"(b[1]));
}
__device__ __forceinline__ void ldsm_x4(uint32_t* d, uint32_t addr) {
    asm volatile("ldmatrix.sync.aligned.m8n8.x4.shared.b16 {%0,%1,%2,%3}, [%4];"
        : "=r"(d[0]), "=r"(d[1]), "=r"(d[2]), "=r"(d[3]) : "r"(addr));
}
__device__ __forceinline__ void cp16(uint32_t dst, const void* src) {
    asm volatile("cp.async.cg.shared.global [%0], [%1], 16;" :: "r"(dst), "l"(src));
}
__device__ __forceinline__ void cp_commit() {
    asm volatile("cp.async.commit_group;" ::: "memory");
}
__device__ __forceinline__ void cp_wait1() {
    asm volatile("cp.async.wait_group 1;" ::: "memory");
}
__device__ __forceinline__ void cp_wait0() {
    asm volatile("cp.async.wait_group 0;" ::: "memory");
}

// ======================= device scratch =======================
__device__ __half g_h0[2][BH];
__device__ __half g_h1[2][BH];
__device__ float g_c0[BH], g_c1[BH];
__device__ float g_ghid[Bv * HHv];
__device__ float g_et[Bv * H4], g_ei[Bv * H4], g_ew[Bv * H4];
__device__ float g_gates[Bv * Ev], g_gacc[Bv * Ev];
__device__ float g_din[2][Bv * 4];

// prepared weights (fp16 hi only; gate-interleaved where applicable)
__device__ __half g_W0hi[H4 * Hv];
__device__ __half g_W1hi[H4 * 2*Hv];
__device__ __half g_Wdhi[H4 * Hv];
__device__ __half g_gWhi[HHv * Hv];
__device__ __half g_tWhi[H4 * Hv];
__device__ __half g_iWhi[H4 * Hv];
__device__ __half g_wWhi[H4 * Hv];
__device__ float g_b0p[H4], g_b1p[H4], g_bdp[H4];
__device__ float g_Ws0[H4 * Fv];   // perm(Wih0) fp32 (side-K)
__device__ float g_Wsd[H4 * 4];    // perm(dec_Wih) fp32 (side-K)

// ======================= single fused prep + init kernel =======================
#define S_W0   (H4 * Hv)
#define S_W1   (H4 * 2 * Hv)
#define S_WD   (H4 * Hv)
#define S_GW   (HHv * Hv)
#define S_TW   (H4 * Hv)
#define S_WS0  (H4 * Fv)
#define S_WSD  (H4 * 4)
#define S_B    (H4)
#define S_INIT (BH)

__global__ void prep_all(const float* enc_Wih0, const float* enc_Whh0, const float* enc_b0,
                         const float* enc_Wih1, const float* enc_Whh1, const float* enc_b1,
                         const float* dec_Wih, const float* dec_Whh, const float* dec_b,
                         const float* gW1, const float* tW1, const float* iW1, const float* wW1)
{
    const long T0 = S_W0, T1 = T0 + S_W1, T2 = T1 + S_WD, T3 = T2 + S_GW;
    const long T4 = T3 + S_TW, T5 = T4 + S_TW, T6 = T5 + S_TW;
    const long T7 = T6 + S_WS0, T8 = T7 + S_WSD, T9 = T8 + 3 * S_B;
    const long TOTAL = T9 + S_INIT;
    for (long i = blockIdx.x * (long)blockDim.x + threadIdx.x; i < TOTAL;
         i += (long)gridDim.x * blockDim.x) {
        if (i < T0) {
            long j = i;
            int n = (int)(j / Hv), k = (int)(j % Hv);
            int orig = (n & 3) * Hv + (n >> 2);
            g_W0hi[j] = __float2half(enc_Whh0[(long)orig * Hv + k]);
        } else if (i < T1) {
            long j = i - T0;
            int n = (int)(j / (2 * Hv)), k = (int)(j % (2 * Hv));
            int orig = (n & 3) * Hv + (n >> 2);
            float v = (k < Hv) ? enc_Wih1[(long)orig * Hv + k]
                               : enc_Whh1[(long)orig * Hv + (k - Hv)];
            g_W1hi[j] = __float2half(v);
        } else if (i < T2) {
            long j = i - T1;
            int n = (int)(j / Hv), k = (int)(j % Hv);
            int orig = (n & 3) * Hv + (n >> 2);
            g_Wdhi[j] = __float2half(dec_Whh[(long)orig * Hv + k]);
        } else if (i < T3) {
            long j = i - T2;
            g_gWhi[j] = __float2half(gW1[j]);
        } else if (i < T4) {
            long j = i - T3;
            g_tWhi[j] = __float2half(tW1[j]);
        } else if (i < T5) {
            long j = i - T4;
            g_iWhi[j] = __float2half(iW1[j]);
        } else if (i < T6) {
            long j = i - T5;
            g_wWhi[j] = __float2half(wW1[j]);
        } else if (i < T7) {
            long j = i - T6;
            int n = (int)(j / Fv), k = (int)(j % Fv);
            int orig = (n & 3) * Hv + (n >> 2);
            g_Ws0[j] = enc_Wih0[(long)orig * Fv + k];
        } else if (i < T8) {
            long j = i - T7;
            int n = (int)(j / 4), k = (int)(j % 4);
            int orig = (n & 3) * Hv + (n >> 2);
            g_Wsd[j] = dec_Wih[(long)orig * 4 + k];
        } else if (i < T9) {
            long j = i - T8;
            int which = (int)(j / S_B), n = (int)(j % S_B);
            int orig = (n & 3) * Hv + (n >> 2);
            if (which == 0)      g_b0p[n] = enc_b0[orig];
            else if (which == 1) g_b1p[n] = enc_b1[orig];
            else                 g_bdp[n] = dec_b[orig];
        } else {
            long j = i - T9;
            g_c0[j] = 0.f; g_c1[j] = 0.f;
            g_h0[0][j] = __float2half(0.f);
            g_h1[0][j] = __float2half(0.f);
            if (j < Bv * 4) g_din[0][j] = 0.f;
            if (j < Bv * Ev) g_gacc[j] = 0.f;
        }
    }
}

// ======================= unified HMMA GEMM core (fp16, single W pass) =======================
// K-chunk = 64 (4 ksteps), 2-stage cp.async pipeline.
// Row pitch 144 B (128 B data + 16 pad): bank stride 36 words mod 32 = 4 -> conflict-free ldmatrix.
#define ROWB  144
#define TILEB (128 * ROWB)              // 18432 B per 128x64 tile
#define STAGEB (2 * TILEB)              // A, Whi per stage (36864 B)
#define SM_BYTES (2 * STAGEB)           // 73728 B double-buffered

__device__ __forceinline__ float sigf(float x) { return 1.f / (1.f + expf(-x)); }

__device__ __forceinline__ void core_gemm(
    char* smem, int m0, int n0,
    const __half* __restrict__ A1, const __half* __restrict__ A2,
    const __half* __restrict__ Whi, int Ktot,
    const float* __restrict__ bias,
    const float* __restrict__ Xs, int ldXs, const float* __restrict__ Wside, int Ks,
    int mode, float* __restrict__ cstate, __half* __restrict__ Hout,
    float* __restrict__ fout, int ldout)
{
    const int tid = threadIdx.x;
    const int wid = tid >> 5, lane = tid & 31;
    const int wm = (wid & 1) * 64;       // warp m-offset
    const int wn = (wid >> 1) * 32;      // warp n-offset
    const uint32_t sb = smem_to_u32(smem);

    float acc[4][4][4];
#pragma unroll
    for (int a = 0; a < 4; a++)
#pragma unroll
        for (int b = 0; b < 4; b++)
#pragma unroll
            for (int d = 0; d < 4; d++) acc[a][b][d] = 0.f;

    const int nch = Ktot / 64;

    auto prefetch = [&](int c, int st) {
        int kg = c * 64;
        const __half* asrc;
        int kloc;
        if (A2 != 0 && kg >= Hv) { asrc = A2; kloc = kg - Hv; }
        else                      { asrc = A1; kloc = kg; }
        uint32_t base = sb + st * STAGEB;
#pragma unroll
        for (int it = 0; it < 4; it++) {
            int idx = tid + it * 256;          // 0..1023
            int r = idx >> 3, q = idx & 7;     // row 0..127, 16B-chunk 0..7
            uint32_t dA = base + r * ROWB + q * 16;
            cp16(dA, (const char*)(asrc + (size_t)(m0 + r) * Hv + kloc) + q * 16);
            uint32_t dW = base + TILEB + r * ROWB + q * 16;
            cp16(dW, (const char*)(Whi + (size_t)(n0 + r) * Ktot + kg) + q * 16);
        }
        cp_commit();
    };

    prefetch(0, 0);

    for (int c = 0; c < nch; c++) {
        if (c + 1 < nch) { prefetch(c + 1, (c + 1) & 1); cp_wait1(); }
        else             { cp_wait0(); }
        __syncthreads();

        uint32_t abase = sb + (c & 1) * STAGEB;
        uint32_t wbase = abase + TILEB;
#pragma unroll
        for (int kstep = 0; kstep < 4; kstep++) {
            uint32_t bhi[4][2], afr[4][4];
            // W fragments: ldmatrix.x4 packs an n-tile pair (both k-halves)
#pragma unroll
            for (int np = 0; np < 2; np++) {
                uint32_t wa = wbase + (wn + np * 16 + ((lane >> 4) * 8) + (lane & 7)) * ROWB
                              + kstep * 32 + ((lane >> 3) & 1) * 16;
                uint32_t d[4];
                ldsm_x4(d, wa);
                bhi[np * 2][0] = d[0]; bhi[np * 2][1] = d[1];
                bhi[np * 2 + 1][0] = d[2]; bhi[np * 2 + 1][1] = d[3];
            }
#pragma unroll
            for (int mt = 0; mt < 4; mt++) {
                uint32_t aa = abase + (wm + mt * 16 + (lane & 15)) * ROWB
                              + kstep * 32 + (lane >> 4) * 16;
                ldsm_x4(afr[mt], aa);
            }
#pragma unroll
            for (int mt = 0; mt < 4; mt++)
#pragma unroll
                for (int nt = 0; nt < 4; nt++) mma16816(acc[mt][nt], afr[mt], bhi[nt]);
        }
        __syncthreads();
    }

    // ---------------- epilogue ----------------
    const int r0 = lane >> 2, cp2 = (lane & 3) * 2;
#pragma unroll
    for (int mt = 0; mt < 4; mt++) {
        int rl = m0 + wm + mt * 16 + r0;     // low row (high row = rl+8)
#pragma unroll
        for (int nt = 0; nt < 4; nt++) {
            float* v = acc[mt][nt];
            int c0 = n0 + wn + nt * 8 + cp2;
            float b0v = bias[c0], b1v = bias[c0 + 1];
            v[0] += b0v; v[1] += b1v; v[2] += b0v; v[3] += b1v;
            if (Ks > 0) {
                const float* xr0 = Xs + (size_t)rl * ldXs;
                const float* xr1 = Xs + (size_t)(rl + 8) * ldXs;
                const float* w0p = Wside + (size_t)c0 * Ks;
                const float* w1p = Wside + (size_t)(c0 + 1) * Ks;
#pragma unroll 4
                for (int k = 0; k < Ks; k++) {
                    float x0 = xr0[k], x1 = xr1[k];
                    float w0 = w0p[k], w1 = w1p[k];
                    v[0] += x0 * w0; v[1] += x0 * w1;
                    v[2] += x1 * w0; v[3] += x1 * w1;
                }
            }
            if (mode == 0) {
                // gate exchange across lane pair (bit0): even lane holds (i,f), odd (g,o)
                float e0 = __shfl_xor_sync(0xffffffffu, v[0], 1);
                float e1 = __shfl_xor_sync(0xffffffffu, v[1], 1);
                float e2 = __shfl_xor_sync(0xffffffffu, v[2], 1);
                float e3 = __shfl_xor_sync(0xffffffffu, v[3], 1);
                float zi, zf, zg, zo;
                int row;
                if ((lane & 1) == 0) { zi = v[0]; zf = v[1]; zg = e0; zo = e1; row = rl; }
                else                 { zi = e2;  zf = e3;  zg = v[2]; zo = v[3]; row = rl + 8; }
                int u = c0 >> 2;
                size_t ci = (size_t)row * Hv + u;
                float cc = sigf(zf) * cstate[ci] + sigf(zi) * tanhf(zg);
                cstate[ci] = cc;
                float hv = sigf(zo) * tanhf(cc);
                Hout[ci] = __float2half(hv);
            } else {
                float2 lo2 = make_float2(fmaxf(v[0], 0.f), fmaxf(v[1], 0.f));
                float2 hi2 = make_float2(fmaxf(v[2], 0.f), fmaxf(v[3], 0.f));
                *(float2*)&fout[(size_t)rl * ldout + c0]       = lo2;
                *(float2*)&fout[(size_t)(rl + 8) * ldout + c0] = hi2;
            }
        }
    }
}

// ======================= kernels wrapping the core =======================
__global__ __launch_bounds__(256, 2) void enc_fused(
    const __half* __restrict__ h0in, const __half* __restrict__ W0hi,
    const float* __restrict__ b0p,
    const float* __restrict__ xt, const float* __restrict__ Ws0,
    float* __restrict__ c0, __half* __restrict__ h0out,
    const __half* __restrict__ h1in, const __half* __restrict__ W1hi,
    const float* __restrict__ b1p,
    float* __restrict__ c1, __half* __restrict__ h1out, int do0, int do1)
{
    extern __shared__ char smem[];
    int m0 = blockIdx.y * 128, n0 = blockIdx.x * 128;
    if (blockIdx.z == 0) {
        if (!do0) return;
        core_gemm(smem, m0, n0, h0in, (const __half*)0, W0hi, Hv, b0p,
                  xt, Sv * Fv, Ws0, Fv, 0, c0, h0out, (float*)0, 0);
    } else {
        if (!do1) return;
        core_gemm(smem, m0, n0, h0in, h1in, W1hi, 2 * Hv, b1p,
                  (const float*)0, 0, (const float*)0, 0, 0, c1, h1out, (float*)0, 0);
    }
}

__global__ __launch_bounds__(256, 2) void dec_lstm(
    const __half* __restrict__ h1in, const __half* __restrict__ Wdhi,
    const float* __restrict__ bdp,
    const float* __restrict__ din, const float* __restrict__ Wsd,
    float* __restrict__ c1, __half* __restrict__ h1out)
{
    extern __shared__ char smem[];
    core_gemm(smem, blockIdx.y * 128, blockIdx.x * 128, h1in, (const __half*)0,
              Wdhi, Hv, bdp, din, 4, Wsd, 4, 0, c1, h1out, (float*)0, 0);
}

__global__ __launch_bounds__(256, 2) void moe_gemm(
    const __half* __restrict__ ctx,
    const __half* __restrict__ gWhi, const float* __restrict__ gb1, float* __restrict__ ghid,
    const __half* __restrict__ tWhi, const float* __restrict__ tb1, float* __restrict__ et,
    const __half* __restrict__ iWhi, const float* __restrict__ ib1, float* __restrict__ ei,
    const __half* __restrict__ wWhi, const float* __restrict__ wb1, float* __restrict__ ew)
{
    extern __shared__ char smem[];
    int j = blockIdx.x, m0 = blockIdx.y * 128;
    const __half* Whi;
    const float* bias;
    float* fo;
    int ld, n0;
    if (j < 2) { Whi = gWhi; bias = gb1; fo = ghid; ld = HHv; n0 = j * 128; }
    else {
        int e = (j - 2) >> 4, jj = (j - 2) & 15;
        n0 = jj * 128; ld = H4;
        if (e == 0)      { Whi = tWhi; bias = tb1; fo = et; }
        else if (e == 1) { Whi = iWhi; bias = ib1; fo = ei; }
        else             { Whi = wWhi; bias = wb1; fo = ew; }
    }
    core_gemm(smem, m0, n0, ctx, (const __half*)0, Whi, Hv, bias,
              (const float*)0, 0, (const float*)0, 0, 1, (float*)0, (__half*)0, fo, ld);
}

// ======================= small fp32 kernels (proven) =======================
__global__ void gating_k(const float* __restrict__ hdd, const float* __restrict__ gW2,
                         const float* __restrict__ gb2, float* __restrict__ gates,
                         float* __restrict__ gacc)
{
    int warp = (blockIdx.x * blockDim.x + threadIdx.x) >> 5;
    int lane = threadIdx.x & 31;
    if (warp >= Bv) return;
    const float* hr = hdd + (size_t)warp * HHv;
    float acc[Ev];
#pragma unroll
    for (int e = 0; e < Ev; e++) acc[e] = 0.f;
    for (int k = lane; k < HHv; k += 32) {
        float hv = hr[k];
#pragma unroll
        for (int e = 0; e < Ev; e++) acc[e] += hv * gW2[e * HHv + k];
    }
#pragma unroll
    for (int e = 0; e < Ev; e++)
#pragma unroll
        for (int o = 16; o > 0; o >>= 1) acc[e] += __shfl_xor_sync(0xffffffffu, acc[e], o);
    if (lane == 0) {
        float lg[Ev], m = -1e30f;
#pragma unroll
        for (int e = 0; e < Ev; e++) { lg[e] = acc[e] + gb2[e]; m = fmaxf(m, lg[e]); }
        float s = 0.f;
#pragma unroll
        for (int e = 0; e < Ev; e++) { lg[e] = expf(lg[e] - m); s += lg[e]; }
        float inv = 1.f / s;
#pragma unroll
        for (int e = 0; e < Ev; e++) {
            float gv = lg[e] * inv;
            gates[warp * Ev + e] = gv;
            gacc[warp * Ev + e] += gv;
        }
    }
}

__global__ void head_comb(const float* __restrict__ et, const float* __restrict__ ei,
                          const float* __restrict__ ew, const float* __restrict__ gates,
                          const float* __restrict__ tW2, const float* __restrict__ tb2,
                          const float* __restrict__ iW2, const float* __restrict__ ib2,
                          const float* __restrict__ wW2, const float* __restrict__ wb2,
                          float* __restrict__ out, float* __restrict__ din_next, int t)
{
    int warp = (blockIdx.x * blockDim.x + threadIdx.x) >> 5;
    int lane = threadIdx.x & 31;
    if (warp >= Bv) return;
    int b = warp;
    float tr0 = 0.f, tr1 = 0.f, dw = 0.f, wd = 0.f;
#pragma unroll
    for (int e = 0; e < Ev; e++) {
        float s0 = 0.f, s1 = 0.f, s2 = 0.f, s3 = 0.f;
        const float* ht = et + (size_t)b * H4 + e * HHv;
        const float* hi = ei + (size_t)b * H4 + e * HHv;
        const float* hw = ew + (size_t)b * H4 + e * HHv;
        const float* t0 = tW2 + (e * 2 + 0) * HHv;
        const float* t1 = tW2 + (e * 2 + 1) * HHv;
        const float* i0 = iW2 + e * HHv;
        const float* w0 = wW2 + e * HHv;
        for (int k = lane; k < HHv; k += 32) {
            float a = ht[k], bb = hi[k], c = hw[k];
            s0 += a * t0[k]; s1 += a * t1[k]; s2 += bb * i0[k]; s3 += c * w0[k];
        }
#pragma unroll
        for (int o = 16; o > 0; o >>= 1) {
            s0 += __shfl_xor_sync(0xffffffffu, s0, o);
            s1 += __shfl_xor_sync(0xffffffffu, s1, o);
            s2 += __shfl_xor_sync(0xffffffffu, s2, o);
            s3 += __shfl_xor_sync(0xffffffffu, s3, o);
        }
        float g = gates[b * Ev + e];
        tr0 += g * (s0 + tb2[e * 2 + 0]);
        tr1 += g * (s1 + tb2[e * 2 + 1]);
        dw  += g * (s2 + ib2[e]);
        wd  += g * (s3 + wb2[e]);
    }
    if (lane == 0) {
        out[(size_t)b * 16 + t]     = tr0;
        out[(size_t)b * 16 + 8 + t] = tr1;
        out[(size_t)Bv * 16 + (size_t)b * 8 + t] = dw;
        out[(size_t)Bv * 24 + (size_t)b * 8 + t] = wd;
        float* dn = din_next + b * 4;
        dn[0] = tr0; dn[1] = tr1; dn[2] = dw; dn[3] = wd;
    }
}

__global__ void fin_k(const float* __restrict__ gacc, float* __restrict__ out)
{
    int i = blockIdx.x * blockDim.x + threadIdx.x;
    if (i < Bv * Ev) out[(size_t)Bv * 32 + i] = gacc[i] * (1.f / HOR);
}

// ======================= launch =======================
extern "C" void kernel_launch(void* const* d_in, const int* in_sizes, int n_in,
                              void* d_out, int out_size)
{
    const float* x        = (const float*)d_in[0];
    const float* enc_Wih0 = (const float*)d_in[1];
    const float* enc_Whh0 = (const float*)d_in[2];
    const float* enc_b0   = (const float*)d_in[3];
    const float* enc_Wih1 = (const float*)d_in[4];
    const float* enc_Whh1 = (const float*)d_in[5];
    const float* enc_b1   = (const float*)d_in[6];
    const float* dec_Wih  = (const float*)d_in[7];
    const float* dec_Whh  = (const float*)d_in[8];
    const float* dec_b    = (const float*)d_in[9];
    const float* gW1      = (const float*)d_in[10];
    const float* gb1      = (const float*)d_in[11];
    const float* gW2      = (const float*)d_in[12];
    const float* gb2      = (const float*)d_in[13];
    const float* tW1      = (const float*)d_in[14];
    const float* tb1      = (const float*)d_in[15];
    const float* tW2      = (const float*)d_in[16];
    const float* tb2      = (const float*)d_in[17];
    const float* iW1      = (const float*)d_in[18];
    const float* ib1      = (const float*)d_in[19];
    const float* iW2      = (const float*)d_in[20];
    const float* ib2      = (const float*)d_in[21];
    const float* wW1      = (const float*)d_in[22];
    const float* wb1      = (const float*)d_in[23];
    const float* wW2      = (const float*)d_in[24];
    const float* wb2      = (const float*)d_in[25];
    float* out = (float*)d_out;

    cudaFuncSetAttribute(enc_fused, cudaFuncAttributeMaxDynamicSharedMemorySize, SM_BYTES);
    cudaFuncSetAttribute(dec_lstm,  cudaFuncAttributeMaxDynamicSharedMemorySize, SM_BYTES);
    cudaFuncSetAttribute(moe_gemm,  cudaFuncAttributeMaxDynamicSharedMemorySize, SM_BYTES);

    __half *h0[2], *h1[2];
    __half *W0hi, *W1hi, *Wdhi, *gWhi, *tWhi, *iWhi, *wWhi;
    float *c0, *c1, *ghid, *et, *ei, *ew, *gates, *gacc, *din, *b0p, *b1p, *bdp, *Ws0, *Wsd;
    {
        void* p;
        cudaGetSymbolAddress(&p, g_h0);   h0[0] = (__half*)p; h0[1] = h0[0] + BH;
        cudaGetSymbolAddress(&p, g_h1);   h1[0] = (__half*)p; h1[1] = h1[0] + BH;
        cudaGetSymbolAddress(&p, g_c0);   c0 = (float*)p;
        cudaGetSymbolAddress(&p, g_c1);   c1 = (float*)p;
        cudaGetSymbolAddress(&p, g_ghid); ghid = (float*)p;
        cudaGetSymbolAddress(&p, g_et);   et = (float*)p;
        cudaGetSymbolAddress(&p, g_ei);   ei = (float*)p;
        cudaGetSymbolAddress(&p, g_ew);   ew = (float*)p;
        cudaGetSymbolAddress(&p, g_gates); gates = (float*)p;
        cudaGetSymbolAddress(&p, g_gacc); gacc = (float*)p;
        cudaGetSymbolAddress(&p, g_din);  din = (float*)p;
        cudaGetSymbolAddress(&p, g_W0hi); W0hi = (__half*)p;
        cudaGetSymbolAddress(&p, g_W1hi); W1hi = (__half*)p;
        cudaGetSymbolAddress(&p, g_Wdhi); Wdhi = (__half*)p;
        cudaGetSymbolAddress(&p, g_gWhi); gWhi = (__half*)p;
        cudaGetSymbolAddress(&p, g_tWhi); tWhi = (__half*)p;
        cudaGetSymbolAddress(&p, g_iWhi); iWhi = (__half*)p;
        cudaGetSymbolAddress(&p, g_wWhi); wWhi = (__half*)p;
        cudaGetSymbolAddress(&p, g_b0p);  b0p = (float*)p;
        cudaGetSymbolAddress(&p, g_b1p);  b1p = (float*)p;
        cudaGetSymbolAddress(&p, g_bdp);  bdp = (float*)p;
        cudaGetSymbolAddress(&p, g_Ws0);  Ws0 = (float*)p;
        cudaGetSymbolAddress(&p, g_Wsd);  Wsd = (float*)p;
    }

    // single fused prep + init launch
    prep_all<<<1024, 256>>>(enc_Wih0, enc_Whh0, enc_b0, enc_Wih1, enc_Whh1, enc_b1,
                            dec_Wih, dec_Whh, dec_b, gW1, tW1, iW1, wW1);

    int p0 = 0, p1 = 0, pd = 0;

    // ---- encoder: skew-pipelined, 65 fused launches ----
    for (int t = 0; t <= Sv; t++) {
        int do0 = (t < Sv) ? 1 : 0;
        int do1 = (t > 0) ? 1 : 0;
        const float* xt = x + (do0 ? t : 0) * Fv;
        enc_fused<<<dim3(16, 16, 2), 256, SM_BYTES>>>(
            h0[p0], W0hi, b0p, xt, Ws0, c0, h0[p0 ^ 1],
            h1[p1], W1hi, b1p, c1, h1[p1 ^ 1], do0, do1);
        if (do0) p0 ^= 1;
        if (do1) p1 ^= 1;
    }

    // ---- decoder: 8 steps ----
    for (int t = 0; t < HOR; t++) {
        dec_lstm<<<dim3(16, 16), 256, SM_BYTES>>>(
            h1[p1], Wdhi, bdp, din + pd * Bv * 4, Wsd, c1, h1[p1 ^ 1]);
        p1 ^= 1;

        moe_gemm<<<dim3(50, 16), 256, SM_BYTES>>>(
            h1[p1],
            gWhi, gb1, ghid,
            tWhi, tb1, et,
            iWhi, ib1, ei,
            wWhi, wb1, ew);

        gating_k<<<Bv / 8, 256>>>(ghid, gW2, gb2, gates, gacc);
        head_comb<<<Bv / 8, 256>>>(et, ei, ew, gates, tW2, tb2, iW2, ib2,
                                   wW2, wb2, out, din + (pd ^ 1) * Bv * 4, t);
        pd ^= 1;
    }

    fin_k<<<(Bv * Ev + 255) / 256, 256>>>(gacc, out);
}

// round 13
// speedup vs baseline: 1.2023x; 1.2023x over previous
#include <cuda_runtime.h>
#include <cuda_fp16.h>
#include <math.h>
#include <stdint.h>

// Problem constants
#define Bv   2048
#define Sv   64
#define Fv   16
#define Hv   512
#define H4   2048
#define Ev   8
#define HHv  256
#define HOR  8
#define BH   (Bv*Hv)

// ======================= portable tensor-op helpers (sm_80+) =======================
__device__ __forceinline__ uint32_t smem_to_u32(const void* p) {
    uint32_t a;
    asm("{ .reg .u64 t; cvta.to.shared.u64 t, %1; cvt.u32.u64 %0, t; }" : "=r"(a) : "l"(p));
    return a;
}
__device__ __forceinline__ void mma16816(float* c, const uint32_t* a, const uint32_t* b) {
    asm volatile("mma.sync.aligned.m16n8k16.row.col.f32.f16.f16.f32 "
        "{%0,%1,%2,%3}, {%4,%5,%6,%7}, {%8,%9}, {%0,%1,%2,%3};"
        : "+f"(c[0]), "+f"(c[1]), "+f"(c[2]), "+f"(c[3])
        : "r"(a[0]), "r"(a[1]), "r"(a[2]), "r"(a[3]), "r"(b[0]), "r"(b[1]));
}
__device__ __forceinline__ void ldsm_x4(uint32_t* d, uint32_t addr) {
    asm volatile("ldmatrix.sync.aligned.m8n8.x4.shared.b16 {%0,%1,%2,%3}, [%4];"
        : "=r"(d[0]), "=r"(d[1]), "=r"(d[2]), "=r"(d[3]) : "r"(addr));
}
__device__ __forceinline__ void cp16(uint32_t dst, const void* src) {
    asm volatile("cp.async.cg.shared.global [%0], [%1], 16;" :: "r"(dst), "l"(src));
}
__device__ __forceinline__ void cp_commit() {
    asm volatile("cp.async.commit_group;" ::: "memory");
}
__device__ __forceinline__ void cp_wait1() {
    asm volatile("cp.async.wait_group 1;" ::: "memory");
}
__device__ __forceinline__ void cp_wait0() {
    asm volatile("cp.async.wait_group 0;" ::: "memory");
}

// ======================= device scratch =======================
__device__ __half g_h0[2][BH];
__device__ __half g_h1[2][BH];
__device__ float g_c0[BH], g_c1[BH];
__device__ float g_ghid[Bv * HHv];
__device__ float g_et[Bv * H4], g_ei[Bv * H4], g_ew[Bv * H4];
__device__ float g_gates[Bv * Ev], g_gacc[Bv * Ev];
__device__ float g_din[2][Bv * 4];

// prepared weights (fp16 hi/lo, gate-interleaved where applicable)
__device__ __half g_W0hi[H4 * Hv],   g_W0lo[H4 * Hv];        // perm(Whh0)
__device__ __half g_W1hi[H4 * 2*Hv], g_W1lo[H4 * 2*Hv];      // perm(cat(Wih1,Whh1))
__device__ __half g_Wdhi[H4 * Hv],   g_Wdlo[H4 * Hv];        // perm(dec_Whh)
__device__ __half g_gWhi[HHv * Hv],  g_gWlo[HHv * Hv];       // gW1
__device__ __half g_tWhi[H4 * Hv],   g_tWlo[H4 * Hv];        // tW1
__device__ __half g_iWhi[H4 * Hv],   g_iWlo[H4 * Hv];        // iW1
__device__ __half g_wWhi[H4 * Hv],   g_wWlo[H4 * Hv];        // wW1
__device__ float g_b0p[H4], g_b1p[H4], g_bdp[H4];
__device__ float g_Ws0[H4 * Fv];   // perm(Wih0) fp32 (side-K)
__device__ float g_Wsd[H4 * 4];    // perm(dec_Wih) fp32 (side-K)

// ======================= single fused prep + init kernel =======================
#define S_W0   (H4 * Hv)
#define S_W1   (H4 * 2 * Hv)
#define S_WD   (H4 * Hv)
#define S_GW   (HHv * Hv)
#define S_TW   (H4 * Hv)
#define S_WS0  (H4 * Fv)
#define S_WSD  (H4 * 4)
#define S_B    (H4)
#define S_INIT (BH)

__device__ __forceinline__ void w_split(__half* hi, __half* lo, long i, float v) {
    __half h = __float2half(v);
    hi[i] = h;
    lo[i] = __float2half(v - __half2float(h));
}

__global__ void prep_all(const float* enc_Wih0, const float* enc_Whh0, const float* enc_b0,
                         const float* enc_Wih1, const float* enc_Whh1, const float* enc_b1,
                         const float* dec_Wih, const float* dec_Whh, const float* dec_b,
                         const float* gW1, const float* tW1, const float* iW1, const float* wW1)
{
    const long T0 = S_W0, T1 = T0 + S_W1, T2 = T1 + S_WD, T3 = T2 + S_GW;
    const long T4 = T3 + S_TW, T5 = T4 + S_TW, T6 = T5 + S_TW;
    const long T7 = T6 + S_WS0, T8 = T7 + S_WSD, T9 = T8 + 3 * S_B;
    const long TOTAL = T9 + S_INIT;
    for (long i = blockIdx.x * (long)blockDim.x + threadIdx.x; i < TOTAL;
         i += (long)gridDim.x * blockDim.x) {
        if (i < T0) {
            long j = i;
            int n = (int)(j / Hv), k = (int)(j % Hv);
            int orig = (n & 3) * Hv + (n >> 2);
            w_split(g_W0hi, g_W0lo, j, enc_Whh0[(long)orig * Hv + k]);
        } else if (i < T1) {
            long j = i - T0;
            int n = (int)(j / (2 * Hv)), k = (int)(j % (2 * Hv));
            int orig = (n & 3) * Hv + (n >> 2);
            float v = (k < Hv) ? enc_Wih1[(long)orig * Hv + k]
                               : enc_Whh1[(long)orig * Hv + (k - Hv)];
            w_split(g_W1hi, g_W1lo, j, v);
        } else if (i < T2) {
            long j = i - T1;
            int n = (int)(j / Hv), k = (int)(j % Hv);
            int orig = (n & 3) * Hv + (n >> 2);
            w_split(g_Wdhi, g_Wdlo, j, dec_Whh[(long)orig * Hv + k]);
        } else if (i < T3) {
            long j = i - T2;
            w_split(g_gWhi, g_gWlo, j, gW1[j]);
        } else if (i < T4) {
            long j = i - T3;
            w_split(g_tWhi, g_tWlo, j, tW1[j]);
        } else if (i < T5) {
            long j = i - T4;
            w_split(g_iWhi, g_iWlo, j, iW1[j]);
        } else if (i < T6) {
            long j = i - T5;
            w_split(g_wWhi, g_wWlo, j, wW1[j]);
        } else if (i < T7) {
            long j = i - T6;
            int n = (int)(j / Fv), k = (int)(j % Fv);
            int orig = (n & 3) * Hv + (n >> 2);
            g_Ws0[j] = enc_Wih0[(long)orig * Fv + k];
        } else if (i < T8) {
            long j = i - T7;
            int n = (int)(j / 4), k = (int)(j % 4);
            int orig = (n & 3) * Hv + (n >> 2);
            g_Wsd[j] = dec_Wih[(long)orig * 4 + k];
        } else if (i < T9) {
            long j = i - T8;
            int which = (int)(j / S_B), n = (int)(j % S_B);
            int orig = (n & 3) * Hv + (n >> 2);
            if (which == 0)      g_b0p[n] = enc_b0[orig];
            else if (which == 1) g_b1p[n] = enc_b1[orig];
            else                 g_bdp[n] = dec_b[orig];
        } else {
            long j = i - T9;
            g_c0[j] = 0.f; g_c1[j] = 0.f;
            g_h0[0][j] = __float2half(0.f);
            g_h1[0][j] = __float2half(0.f);
            if (j < Bv * 4) g_din[0][j] = 0.f;
            if (j < Bv * Ev) g_gacc[j] = 0.f;
        }
    }
}

// ======================= unified HMMA GEMM core (fp16 x2: A*Whi + A*Wlo) =======================
// K-chunk = 64 (4 ksteps), 2-stage cp.async pipeline.  (R11 configuration — best measured)
#define ROWB  144
#define TILEB (128 * ROWB)              // 18432 B per 128x64 tile
#define STAGEB (3 * TILEB)              // A, Whi, Wlo per stage (55296 B)
#define SM_BYTES (2 * STAGEB)           // 110592 B double-buffered

__device__ __forceinline__ float sigf(float x) { return 1.f / (1.f + expf(-x)); }

__device__ __forceinline__ void core_gemm(
    char* smem, int m0, int n0,
    const __half* __restrict__ A1, const __half* __restrict__ A2,
    const __half* __restrict__ Whi, const __half* __restrict__ Wlo, int Ktot,
    const float* __restrict__ bias,
    const float* __restrict__ Xs, int ldXs, const float* __restrict__ Wside, int Ks,
    int mode, float* __restrict__ cstate, __half* __restrict__ Hout,
    float* __restrict__ fout, int ldout)
{
    const int tid = threadIdx.x;
    const int wid = tid >> 5, lane = tid & 31;
    const int wm = (wid & 1) * 64;       // warp m-offset
    const int wn = (wid >> 1) * 32;      // warp n-offset
    const uint32_t sb = smem_to_u32(smem);

    float acc[4][4][4];
#pragma unroll
    for (int a = 0; a < 4; a++)
#pragma unroll
        for (int b = 0; b < 4; b++)
#pragma unroll
            for (int d = 0; d < 4; d++) acc[a][b][d] = 0.f;

    const int nch = Ktot / 64;

    auto prefetch = [&](int c, int st) {
        int kg = c * 64;
        const __half* asrc;
        int kloc;
        if (A2 != 0 && kg >= Hv) { asrc = A2; kloc = kg - Hv; }
        else                      { asrc = A1; kloc = kg; }
        uint32_t base = sb + st * STAGEB;
#pragma unroll
        for (int it = 0; it < 4; it++) {
            int idx = tid + it * 256;          // 0..1023
            int r = idx >> 3, q = idx & 7;     // row 0..127, 16B-chunk 0..7
            uint32_t dA = base + r * ROWB + q * 16;
            cp16(dA, (const char*)(asrc + (size_t)(m0 + r) * Hv + kloc) + q * 16);
            uint32_t dW = base + TILEB + r * ROWB + q * 16;
            cp16(dW, (const char*)(Whi + (size_t)(n0 + r) * Ktot + kg) + q * 16);
            cp16(dW + TILEB, (const char*)(Wlo + (size_t)(n0 + r) * Ktot + kg) + q * 16);
        }
        cp_commit();
    };

    prefetch(0, 0);

    for (int c = 0; c < nch; c++) {
        if (c + 1 < nch) { prefetch(c + 1, (c + 1) & 1); cp_wait1(); }
        else             { cp_wait0(); }
        __syncthreads();

        uint32_t abase = sb + (c & 1) * STAGEB;
        uint32_t wbase = abase + TILEB;
#pragma unroll
        for (int kstep = 0; kstep < 4; kstep++) {
            uint32_t bhi[4][2], blo[4][2], afr[4][4];
            // W fragments: ldmatrix.x4 packs an n-tile pair (both k-halves)
#pragma unroll
            for (int np = 0; np < 2; np++) {
                uint32_t wa = wbase + (wn + np * 16 + ((lane >> 4) * 8) + (lane & 7)) * ROWB
                              + kstep * 32 + ((lane >> 3) & 1) * 16;
                uint32_t d[4];
                ldsm_x4(d, wa);
                bhi[np * 2][0] = d[0]; bhi[np * 2][1] = d[1];
                bhi[np * 2 + 1][0] = d[2]; bhi[np * 2 + 1][1] = d[3];
                ldsm_x4(d, wa + TILEB);
                blo[np * 2][0] = d[0]; blo[np * 2][1] = d[1];
                blo[np * 2 + 1][0] = d[2]; blo[np * 2 + 1][1] = d[3];
            }
#pragma unroll
            for (int mt = 0; mt < 4; mt++) {
                uint32_t aa = abase + (wm + mt * 16 + (lane & 15)) * ROWB
                              + kstep * 32 + (lane >> 4) * 16;
                ldsm_x4(afr[mt], aa);
            }
#pragma unroll
            for (int mt = 0; mt < 4; mt++)
#pragma unroll
                for (int nt = 0; nt < 4; nt++) mma16816(acc[mt][nt], afr[mt], bhi[nt]);
#pragma unroll
            for (int mt = 0; mt < 4; mt++)
#pragma unroll
                for (int nt = 0; nt < 4; nt++) mma16816(acc[mt][nt], afr[mt], blo[nt]);
        }
        __syncthreads();
    }

    // ---------------- epilogue (register-lean: no cached side-K arrays) ----------------
    const int r0 = lane >> 2, cp2 = (lane & 3) * 2;
#pragma unroll
    for (int mt = 0; mt < 4; mt++) {
        int rl = m0 + wm + mt * 16 + r0;     // low row (high row = rl+8)
#pragma unroll
        for (int nt = 0; nt < 4; nt++) {
            float* v = acc[mt][nt];
            int c0 = n0 + wn + nt * 8 + cp2;
            float b0v = bias[c0], b1v = bias[c0 + 1];
            v[0] += b0v; v[1] += b1v; v[2] += b0v; v[3] += b1v;
            if (Ks > 0) {
                const float* xr0 = Xs + (size_t)rl * ldXs;
                const float* xr1 = Xs + (size_t)(rl + 8) * ldXs;
                const float* w0p = Wside + (size_t)c0 * Ks;
                const float* w1p = Wside + (size_t)(c0 + 1) * Ks;
#pragma unroll 4
                for (int k = 0; k < Ks; k++) {
                    float x0 = xr0[k], x1 = xr1[k];
                    float w0 = w0p[k], w1 = w1p[k];
                    v[0] += x0 * w0; v[1] += x0 * w1;
                    v[2] += x1 * w0; v[3] += x1 * w1;
                }
            }
            if (mode == 0) {
                // gate exchange across lane pair (bit0): even lane holds (i,f), odd (g,o)
                float e0 = __shfl_xor_sync(0xffffffffu, v[0], 1);
                float e1 = __shfl_xor_sync(0xffffffffu, v[1], 1);
                float e2 = __shfl_xor_sync(0xffffffffu, v[2], 1);
                float e3 = __shfl_xor_sync(0xffffffffu, v[3], 1);
                float zi, zf, zg, zo;
                int row;
                if ((lane & 1) == 0) { zi = v[0]; zf = v[1]; zg = e0; zo = e1; row = rl; }
                else                 { zi = e2;  zf = e3;  zg = v[2]; zo = v[3]; row = rl + 8; }
                int u = c0 >> 2;
                size_t ci = (size_t)row * Hv + u;
                float cc = sigf(zf) * cstate[ci] + sigf(zi) * tanhf(zg);
                cstate[ci] = cc;
                float hv = sigf(zo) * tanhf(cc);
                Hout[ci] = __float2half(hv);
            } else {
                float2 lo2 = make_float2(fmaxf(v[0], 0.f), fmaxf(v[1], 0.f));
                float2 hi2 = make_float2(fmaxf(v[2], 0.f), fmaxf(v[3], 0.f));
                *(float2*)&fout[(size_t)rl * ldout + c0]       = lo2;
                *(float2*)&fout[(size_t)(rl + 8) * ldout + c0] = hi2;
            }
        }
    }
}

// ======================= kernels wrapping the core =======================
// Fused encoder step, longest-job-first: z=0 -> layer1 (K=1024, step t-1);
// z=1 -> layer0 (K=512, step t). Long CTAs get low block IDs -> scheduled first.
__global__ __launch_bounds__(256, 2) void enc_fused(
    const __half* __restrict__ h0in, const __half* __restrict__ W0hi,
    const __half* __restrict__ W0lo, const float* __restrict__ b0p,
    const float* __restrict__ xt, const float* __restrict__ Ws0,
    float* __restrict__ c0, __half* __restrict__ h0out,
    const __half* __restrict__ h1in, const __half* __restrict__ W1hi,
    const __half* __restrict__ W1lo, const float* __restrict__ b1p,
    float* __restrict__ c1, __half* __restrict__ h1out, int do0, int do1)
{
    extern __shared__ char smem[];
    int m0 = blockIdx.y * 128, n0 = blockIdx.x * 128;
    if (blockIdx.z == 0) {
        if (!do1) return;
        core_gemm(smem, m0, n0, h0in, h1in, W1hi, W1lo, 2 * Hv, b1p,
                  (const float*)0, 0, (const float*)0, 0, 0, c1, h1out, (float*)0, 0);
    } else {
        if (!do0) return;
        core_gemm(smem, m0, n0, h0in, (const __half*)0, W0hi, W0lo, Hv, b0p,
                  xt, Sv * Fv, Ws0, Fv, 0, c0, h0out, (float*)0, 0);
    }
}

// Decoder LSTM step
__global__ __launch_bounds__(256, 2) void dec_lstm(
    const __half* __restrict__ h1in, const __half* __restrict__ Wdhi,
    const __half* __restrict__ Wdlo, const float* __restrict__ bdp,
    const float* __restrict__ din, const float* __restrict__ Wsd,
    float* __restrict__ c1, __half* __restrict__ h1out)
{
    extern __shared__ char smem[];
    core_gemm(smem, blockIdx.y * 128, blockIdx.x * 128, h1in, (const __half*)0,
              Wdhi, Wdlo, Hv, bdp, din, 4, Wsd, 4, 0, c1, h1out, (float*)0, 0);
}

// Fused MoE: gating layer1 (2 n-tiles) + 3 expert layer1s (16 n-tiles each)
__global__ __launch_bounds__(256, 2) void moe_gemm(
    const __half* __restrict__ ctx,
    const __half* __restrict__ gWhi, const __half* __restrict__ gWlo,
    const float* __restrict__ gb1, float* __restrict__ ghid,
    const __half* __restrict__ tWhi, const __half* __restrict__ tWlo,
    const float* __restrict__ tb1, float* __restrict__ et,
    const __half* __restrict__ iWhi, const __half* __restrict__ iWlo,
    const float* __restrict__ ib1, float* __restrict__ ei,
    const __half* __restrict__ wWhi, const __half* __restrict__ wWlo,
    const float* __restrict__ wb1, float* __restrict__ ew)
{
    extern __shared__ char smem[];
    int j = blockIdx.x, m0 = blockIdx.y * 128;
    const __half *Whi, *Wlo;
    const float* bias;
    float* fo;
    int ld, n0;
    if (j < 2) { Whi = gWhi; Wlo = gWlo; bias = gb1; fo = ghid; ld = HHv; n0 = j * 128; }
    else {
        int e = (j - 2) >> 4, jj = (j - 2) & 15;
        n0 = jj * 128; ld = H4;
        if (e == 0)      { Whi = tWhi; Wlo = tWlo; bias = tb1; fo = et; }
        else if (e == 1) { Whi = iWhi; Wlo = iWlo; bias = ib1; fo = ei; }
        else             { Whi = wWhi; Wlo = wWlo; bias = wb1; fo = ew; }
    }
    core_gemm(smem, m0, n0, ctx, (const __half*)0, Whi, Wlo, Hv, bias,
              (const float*)0, 0, (const float*)0, 0, 1, (float*)0, (__half*)0, fo, ld);
}

// ======================= small fp32 kernels (proven) =======================
__global__ void gating_k(const float* __restrict__ hdd, const float* __restrict__ gW2,
                         const float* __restrict__ gb2, float* __restrict__ gates,
                         float* __restrict__ gacc)
{
    int warp = (blockIdx.x * blockDim.x + threadIdx.x) >> 5;
    int lane = threadIdx.x & 31;
    if (warp >= Bv) return;
    const float* hr = hdd + (size_t)warp * HHv;
    float acc[Ev];
#pragma unroll
    for (int e = 0; e < Ev; e++) acc[e] = 0.f;
    for (int k = lane; k < HHv; k += 32) {
        float hv = hr[k];
#pragma unroll
        for (int e = 0; e < Ev; e++) acc[e] += hv * gW2[e * HHv + k];
    }
#pragma unroll
    for (int e = 0; e < Ev; e++)
#pragma unroll
        for (int o = 16; o > 0; o >>= 1) acc[e] += __shfl_xor_sync(0xffffffffu, acc[e], o);
    if (lane == 0) {
        float lg[Ev], m = -1e30f;
#pragma unroll
        for (int e = 0; e < Ev; e++) { lg[e] = acc[e] + gb2[e]; m = fmaxf(m, lg[e]); }
        float s = 0.f;
#pragma unroll
        for (int e = 0; e < Ev; e++) { lg[e] = expf(lg[e] - m); s += lg[e]; }
        float inv = 1.f / s;
#pragma unroll
        for (int e = 0; e < Ev; e++) {
            float gv = lg[e] * inv;
            gates[warp * Ev + e] = gv;
            gacc[warp * Ev + e] += gv;
        }
    }
}

__global__ void head_comb(const float* __restrict__ et, const float* __restrict__ ei,
                          const float* __restrict__ ew, const float* __restrict__ gates,
                          const float* __restrict__ tW2, const float* __restrict__ tb2,
                          const float* __restrict__ iW2, const float* __restrict__ ib2,
                          const float* __restrict__ wW2, const float* __restrict__ wb2,
                          float* __restrict__ out, float* __restrict__ din_next, int t)
{
    int warp = (blockIdx.x * blockDim.x + threadIdx.x) >> 5;
    int lane = threadIdx.x & 31;
    if (warp >= Bv) return;
    int b = warp;
    float tr0 = 0.f, tr1 = 0.f, dw = 0.f, wd = 0.f;
#pragma unroll
    for (int e = 0; e < Ev; e++) {
        float s0 = 0.f, s1 = 0.f, s2 = 0.f, s3 = 0.f;
        const float* ht = et + (size_t)b * H4 + e * HHv;
        const float* hi = ei + (size_t)b * H4 + e * HHv;
        const float* hw = ew + (size_t)b * H4 + e * HHv;
        const float* t0 = tW2 + (e * 2 + 0) * HHv;
        const float* t1 = tW2 + (e * 2 + 1) * HHv;
        const float* i0 = iW2 + e * HHv;
        const float* w0 = wW2 + e * HHv;
        for (int k = lane; k < HHv; k += 32) {
            float a = ht[k], bb = hi[k], c = hw[k];
            s0 += a * t0[k]; s1 += a * t1[k]; s2 += bb * i0[k]; s3 += c * w0[k];
        }
#pragma unroll
        for (int o = 16; o > 0; o >>= 1) {
            s0 += __shfl_xor_sync(0xffffffffu, s0, o);
            s1 += __shfl_xor_sync(0xffffffffu, s1, o);
            s2 += __shfl_xor_sync(0xffffffffu, s2, o);
            s3 += __shfl_xor_sync(0xffffffffu, s3, o);
        }
        float g = gates[b * Ev + e];
        tr0 += g * (s0 + tb2[e * 2 + 0]);
        tr1 += g * (s1 + tb2[e * 2 + 1]);
        dw  += g * (s2 + ib2[e]);
        wd  += g * (s3 + wb2[e]);
    }
    if (lane == 0) {
        out[(size_t)b * 16 + t]     = tr0;
        out[(size_t)b * 16 + 8 + t] = tr1;
        out[(size_t)Bv * 16 + (size_t)b * 8 + t] = dw;
        out[(size_t)Bv * 24 + (size_t)b * 8 + t] = wd;
        float* dn = din_next + b * 4;
        dn[0] = tr0; dn[1] = tr1; dn[2] = dw; dn[3] = wd;
    }
}

__global__ void fin_k(const float* __restrict__ gacc, float* __restrict__ out)
{
    int i = blockIdx.x * blockDim.x + threadIdx.x;
    if (i < Bv * Ev) out[(size_t)Bv * 32 + i] = gacc[i] * (1.f / HOR);
}

// ======================= launch =======================
extern "C" void kernel_launch(void* const* d_in, const int* in_sizes, int n_in,
                              void* d_out, int out_size)
{
    const float* x        = (const float*)d_in[0];
    const float* enc_Wih0 = (const float*)d_in[1];
    const float* enc_Whh0 = (const float*)d_in[2];
    const float* enc_b0   = (const float*)d_in[3];
    const float* enc_Wih1 = (const float*)d_in[4];
    const float* enc_Whh1 = (const float*)d_in[5];
    const float* enc_b1   = (const float*)d_in[6];
    const float* dec_Wih  = (const float*)d_in[7];
    const float* dec_Whh  = (const float*)d_in[8];
    const float* dec_b    = (const float*)d_in[9];
    const float* gW1      = (const float*)d_in[10];
    const float* gb1      = (const float*)d_in[11];
    const float* gW2      = (const float*)d_in[12];
    const float* gb2      = (const float*)d_in[13];
    const float* tW1      = (const float*)d_in[14];
    const float* tb1      = (const float*)d_in[15];
    const float* tW2      = (const float*)d_in[16];
    const float* tb2      = (const float*)d_in[17];
    const float* iW1      = (const float*)d_in[18];
    const float* ib1      = (const float*)d_in[19];
    const float* iW2      = (const float*)d_in[20];
    const float* ib2      = (const float*)d_in[21];
    const float* wW1      = (const float*)d_in[22];
    const float* wb1      = (const float*)d_in[23];
    const float* wW2      = (const float*)d_in[24];
    const float* wb2      = (const float*)d_in[25];
    float* out = (float*)d_out;

    cudaFuncSetAttribute(enc_fused, cudaFuncAttributeMaxDynamicSharedMemorySize, SM_BYTES);
    cudaFuncSetAttribute(dec_lstm,  cudaFuncAttributeMaxDynamicSharedMemorySize, SM_BYTES);
    cudaFuncSetAttribute(moe_gemm,  cudaFuncAttributeMaxDynamicSharedMemorySize, SM_BYTES);

    __half *h0[2], *h1[2];
    __half *W0hi, *W0lo, *W1hi, *W1lo, *Wdhi, *Wdlo;
    __half *gWhi, *gWlo, *tWhi, *tWlo, *iWhi, *iWlo, *wWhi, *wWlo;
    float *c0, *c1, *ghid, *et, *ei, *ew, *gates, *gacc, *din, *b0p, *b1p, *bdp, *Ws0, *Wsd;
    {
        void* p;
        cudaGetSymbolAddress(&p, g_h0);   h0[0] = (__half*)p; h0[1] = h0[0] + BH;
        cudaGetSymbolAddress(&p, g_h1);   h1[0] = (__half*)p; h1[1] = h1[0] + BH;
        cudaGetSymbolAddress(&p, g_c0);   c0 = (float*)p;
        cudaGetSymbolAddress(&p, g_c1);   c1 = (float*)p;
        cudaGetSymbolAddress(&p, g_ghid); ghid = (float*)p;
        cudaGetSymbolAddress(&p, g_et);   et = (float*)p;
        cudaGetSymbolAddress(&p, g_ei);   ei = (float*)p;
        cudaGetSymbolAddress(&p, g_ew);   ew = (float*)p;
        cudaGetSymbolAddress(&p, g_gates); gates = (float*)p;
        cudaGetSymbolAddress(&p, g_gacc); gacc = (float*)p;
        cudaGetSymbolAddress(&p, g_din);  din = (float*)p;
        cudaGetSymbolAddress(&p, g_W0hi); W0hi = (__half*)p;
        cudaGetSymbolAddress(&p, g_W0lo); W0lo = (__half*)p;
        cudaGetSymbolAddress(&p, g_W1hi); W1hi = (__half*)p;
        cudaGetSymbolAddress(&p, g_W1lo); W1lo = (__half*)p;
        cudaGetSymbolAddress(&p, g_Wdhi); Wdhi = (__half*)p;
        cudaGetSymbolAddress(&p, g_Wdlo); Wdlo = (__half*)p;
        cudaGetSymbolAddress(&p, g_gWhi); gWhi = (__half*)p;
        cudaGetSymbolAddress(&p, g_gWlo); gWlo = (__half*)p;
        cudaGetSymbolAddress(&p, g_tWhi); tWhi = (__half*)p;
        cudaGetSymbolAddress(&p, g_tWlo); tWlo = (__half*)p;
        cudaGetSymbolAddress(&p, g_iWhi); iWhi = (__half*)p;
        cudaGetSymbolAddress(&p, g_iWlo); iWlo = (__half*)p;
        cudaGetSymbolAddress(&p, g_wWhi); wWhi = (__half*)p;
        cudaGetSymbolAddress(&p, g_wWlo); wWlo = (__half*)p;
        cudaGetSymbolAddress(&p, g_b0p);  b0p = (float*)p;
        cudaGetSymbolAddress(&p, g_b1p);  b1p = (float*)p;
        cudaGetSymbolAddress(&p, g_bdp);  bdp = (float*)p;
        cudaGetSymbolAddress(&p, g_Ws0);  Ws0 = (float*)p;
        cudaGetSymbolAddress(&p, g_Wsd);  Wsd = (float*)p;
    }

    // single fused prep + init launch
    prep_all<<<1024, 256>>>(enc_Wih0, enc_Whh0, enc_b0, enc_Wih1, enc_Whh1, enc_b1,
                            dec_Wih, dec_Whh, dec_b, gW1, tW1, iW1, wW1);

    int p0 = 0, p1 = 0, pd = 0;

    // ---- encoder: skew-pipelined, 65 fused launches ----
    for (int t = 0; t <= Sv; t++) {
        int do0 = (t < Sv) ? 1 : 0;
        int do1 = (t > 0) ? 1 : 0;
        const float* xt = x + (do0 ? t : 0) * Fv;
        enc_fused<<<dim3(16, 16, 2), 256, SM_BYTES>>>(
            h0[p0], W0hi, W0lo, b0p, xt, Ws0, c0, h0[p0 ^ 1],
            h1[p1], W1hi, W1lo, b1p, c1, h1[p1 ^ 1], do0, do1);
        if (do0) p0 ^= 1;
        if (do1) p1 ^= 1;
    }

    // ---- decoder: 8 steps ----
    for (int t = 0; t < HOR; t++) {
        dec_lstm<<<dim3(16, 16), 256, SM_BYTES>>>(
            h1[p1], Wdhi, Wdlo, bdp, din + pd * Bv * 4, Wsd, c1, h1[p1 ^ 1]);
        p1 ^= 1;

        moe_gemm<<<dim3(50, 16), 256, SM_BYTES>>>(
            h1[p1],
            gWhi, gWlo, gb1, ghid,
            tWhi, tWlo, tb1, et,
            iWhi, iWlo, ib1, ei,
            wWhi, wWlo, wb1, ew);

        gating_k<<<Bv / 8, 256>>>(ghid, gW2, gb2, gates, gacc);
        head_comb<<<Bv / 8, 256>>>(et, ei, ew, gates, tW2, tb2, iW2, ib2,
                                   wW2, wb2, out, din + (pd ^ 1) * Bv * 4, t);
        pd ^= 1;
    }

    fin_k<<<(Bv * Ev + 255) / 256, 256>>>(gacc, out);
}

// round 14
// speedup vs baseline: 1.2214x; 1.0159x over previous
#include <cuda_runtime.h>
#include <cuda_fp16.h>
#include <math.h>
#include <stdint.h>

// Problem constants
#define Bv   2048
#define Sv   64
#define Fv   16
#define Hv   512
#define H4   2048
#define Ev   8
#define HHv  256
#define HOR  8
#define BH   (Bv*Hv)

// ======================= portable tensor-op helpers (sm_80+) =======================
__device__ __forceinline__ uint32_t smem_to_u32(const void* p) {
    uint32_t a;
    asm("{ .reg .u64 t; cvta.to.shared.u64 t, %1; cvt.u32.u64 %0, t; }" : "=r"(a) : "l"(p));
    return a;
}
__device__ __forceinline__ void mma16816(float* c, const uint32_t* a, const uint32_t* b) {
    asm volatile("mma.sync.aligned.m16n8k16.row.col.f32.f16.f16.f32 "
        "{%0,%1,%2,%3}, {%4,%5,%6,%7}, {%8,%9}, {%0,%1,%2,%3};"
        : "+f"(c[0]), "+f"(c[1]), "+f"(c[2]), "+f"(c[3])
        : "r"(a[0]), "r"(a[1]), "r"(a[2]), "r"(a[3]), "r"(b[0]), "r"(b[1]));
}
__device__ __forceinline__ void ldsm_x4(uint32_t* d, uint32_t addr) {
    asm volatile("ldmatrix.sync.aligned.m8n8.x4.shared.b16 {%0,%1,%2,%3}, [%4];"
        : "=r"(d[0]), "=r"(d[1]), "=r"(d[2]), "=r"(d[3]) : "r"(addr));
}
__device__ __forceinline__ void cp16(uint32_t dst, const void* src) {
    asm volatile("cp.async.cg.shared.global [%0], [%1], 16;" :: "r"(dst), "l"(src));
}
__device__ __forceinline__ void cp_commit() {
    asm volatile("cp.async.commit_group;" ::: "memory");
}
__device__ __forceinline__ void cp_wait1() {
    asm volatile("cp.async.wait_group 1;" ::: "memory");
}
__device__ __forceinline__ void cp_wait0() {
    asm volatile("cp.async.wait_group 0;" ::: "memory");
}

// fast transcendentals: hardware EX2 path, saturating, rel err ~2^-21
__device__ __forceinline__ float sigf(float x)      { return 1.f / (1.f + __expf(-x)); }
__device__ __forceinline__ float tanhfast(float x)  { return 1.f - 2.f / (__expf(2.f * x) + 1.f); }

// ======================= device scratch =======================
__device__ __half g_h0[2][BH];
__device__ __half g_h1[2][BH];
__device__ float g_c0[BH], g_c1[BH];
__device__ float g_ghid[Bv * HHv];
__device__ float g_et[Bv * H4], g_ei[Bv * H4], g_ew[Bv * H4];
__device__ float g_gacc[Bv * Ev];
__device__ float g_din[2][Bv * 4];

// prepared weights (fp16 hi/lo, gate-interleaved where applicable)
__device__ __half g_W0hi[H4 * Hv],   g_W0lo[H4 * Hv];        // perm(Whh0)
__device__ __half g_W1hi[H4 * 2*Hv], g_W1lo[H4 * 2*Hv];      // perm(cat(Wih1,Whh1))
__device__ __half g_Wdhi[H4 * Hv],   g_Wdlo[H4 * Hv];        // perm(dec_Whh)
__device__ __half g_gWhi[HHv * Hv],  g_gWlo[HHv * Hv];       // gW1
__device__ __half g_tWhi[H4 * Hv],   g_tWlo[H4 * Hv];        // tW1
__device__ __half g_iWhi[H4 * Hv],   g_iWlo[H4 * Hv];        // iW1
__device__ __half g_wWhi[H4 * Hv],   g_wWlo[H4 * Hv];        // wW1
__device__ float g_b0p[H4], g_b1p[H4], g_bdp[H4];
__device__ float g_Ws0[H4 * Fv];   // perm(Wih0) fp32 (side-K)
__device__ float g_Wsd[H4 * 4];    // perm(dec_Wih) fp32 (side-K)

// ======================= single fused prep + init kernel =======================
#define S_W0   (H4 * Hv)
#define S_W1   (H4 * 2 * Hv)
#define S_WD   (H4 * Hv)
#define S_GW   (HHv * Hv)
#define S_TW   (H4 * Hv)
#define S_WS0  (H4 * Fv)
#define S_WSD  (H4 * 4)
#define S_B    (H4)
#define S_INIT (BH)

__device__ __forceinline__ void w_split(__half* hi, __half* lo, long i, float v) {
    __half h = __float2half(v);
    hi[i] = h;
    lo[i] = __float2half(v - __half2float(h));
}

__global__ void prep_all(const float* enc_Wih0, const float* enc_Whh0, const float* enc_b0,
                         const float* enc_Wih1, const float* enc_Whh1, const float* enc_b1,
                         const float* dec_Wih, const float* dec_Whh, const float* dec_b,
                         const float* gW1, const float* tW1, const float* iW1, const float* wW1)
{
    const long T0 = S_W0, T1 = T0 + S_W1, T2 = T1 + S_WD, T3 = T2 + S_GW;
    const long T4 = T3 + S_TW, T5 = T4 + S_TW, T6 = T5 + S_TW;
    const long T7 = T6 + S_WS0, T8 = T7 + S_WSD, T9 = T8 + 3 * S_B;
    const long TOTAL = T9 + S_INIT;
    for (long i = blockIdx.x * (long)blockDim.x + threadIdx.x; i < TOTAL;
         i += (long)gridDim.x * blockDim.x) {
        if (i < T0) {
            long j = i;
            int n = (int)(j / Hv), k = (int)(j % Hv);
            int orig = (n & 3) * Hv + (n >> 2);
            w_split(g_W0hi, g_W0lo, j, enc_Whh0[(long)orig * Hv + k]);
        } else if (i < T1) {
            long j = i - T0;
            int n = (int)(j / (2 * Hv)), k = (int)(j % (2 * Hv));
            int orig = (n & 3) * Hv + (n >> 2);
            float v = (k < Hv) ? enc_Wih1[(long)orig * Hv + k]
                               : enc_Whh1[(long)orig * Hv + (k - Hv)];
            w_split(g_W1hi, g_W1lo, j, v);
        } else if (i < T2) {
            long j = i - T1;
            int n = (int)(j / Hv), k = (int)(j % Hv);
            int orig = (n & 3) * Hv + (n >> 2);
            w_split(g_Wdhi, g_Wdlo, j, dec_Whh[(long)orig * Hv + k]);
        } else if (i < T3) {
            long j = i - T2;
            w_split(g_gWhi, g_gWlo, j, gW1[j]);
        } else if (i < T4) {
            long j = i - T3;
            w_split(g_tWhi, g_tWlo, j, tW1[j]);
        } else if (i < T5) {
            long j = i - T4;
            w_split(g_iWhi, g_iWlo, j, iW1[j]);
        } else if (i < T6) {
            long j = i - T5;
            w_split(g_wWhi, g_wWlo, j, wW1[j]);
        } else if (i < T7) {
            long j = i - T6;
            int n = (int)(j / Fv), k = (int)(j % Fv);
            int orig = (n & 3) * Hv + (n >> 2);
            g_Ws0[j] = enc_Wih0[(long)orig * Fv + k];
        } else if (i < T8) {
            long j = i - T7;
            int n = (int)(j / 4), k = (int)(j % 4);
            int orig = (n & 3) * Hv + (n >> 2);
            g_Wsd[j] = dec_Wih[(long)orig * 4 + k];
        } else if (i < T9) {
            long j = i - T8;
            int which = (int)(j / S_B), n = (int)(j % S_B);
            int orig = (n & 3) * Hv + (n >> 2);
            if (which == 0)      g_b0p[n] = enc_b0[orig];
            else if (which == 1) g_b1p[n] = enc_b1[orig];
            else                 g_bdp[n] = dec_b[orig];
        } else {
            long j = i - T9;
            g_c0[j] = 0.f; g_c1[j] = 0.f;
            g_h0[0][j] = __float2half(0.f);
            g_h1[0][j] = __float2half(0.f);
            if (j < Bv * 4) g_din[0][j] = 0.f;
            if (j < Bv * Ev) g_gacc[j] = 0.f;
        }
    }
}

// ======================= unified HMMA GEMM core (fp16 x2: A*Whi + A*Wlo) =======================
// K-chunk = 64 (4 ksteps), 2-stage cp.async pipeline.  (R11/R13 configuration — best measured)
#define ROWB  144
#define TILEB (128 * ROWB)              // 18432 B per 128x64 tile
#define STAGEB (3 * TILEB)              // A, Whi, Wlo per stage (55296 B)
#define SM_BYTES (2 * STAGEB)           // 110592 B double-buffered

__device__ __forceinline__ void core_gemm(
    char* smem, int m0, int n0,
    const __half* __restrict__ A1, const __half* __restrict__ A2,
    const __half* __restrict__ Whi, const __half* __restrict__ Wlo, int Ktot,
    const float* __restrict__ bias,
    const float* __restrict__ Xs, int ldXs, const float* __restrict__ Wside, int Ks,
    int mode, float* __restrict__ cstate, __half* __restrict__ Hout,
    float* __restrict__ fout, int ldout)
{
    const int tid = threadIdx.x;
    const int wid = tid >> 5, lane = tid & 31;
    const int wm = (wid & 1) * 64;       // warp m-offset
    const int wn = (wid >> 1) * 32;      // warp n-offset
    const uint32_t sb = smem_to_u32(smem);

    float acc[4][4][4];
#pragma unroll
    for (int a = 0; a < 4; a++)
#pragma unroll
        for (int b = 0; b < 4; b++)
#pragma unroll
            for (int d = 0; d < 4; d++) acc[a][b][d] = 0.f;

    const int nch = Ktot / 64;

    auto prefetch = [&](int c, int st) {
        int kg = c * 64;
        const __half* asrc;
        int kloc;
        if (A2 != 0 && kg >= Hv) { asrc = A2; kloc = kg - Hv; }
        else                      { asrc = A1; kloc = kg; }
        uint32_t base = sb + st * STAGEB;
#pragma unroll
        for (int it = 0; it < 4; it++) {
            int idx = tid + it * 256;          // 0..1023
            int r = idx >> 3, q = idx & 7;     // row 0..127, 16B-chunk 0..7
            uint32_t dA = base + r * ROWB + q * 16;
            cp16(dA, (const char*)(asrc + (size_t)(m0 + r) * Hv + kloc) + q * 16);
            uint32_t dW = base + TILEB + r * ROWB + q * 16;
            cp16(dW, (const char*)(Whi + (size_t)(n0 + r) * Ktot + kg) + q * 16);
            cp16(dW + TILEB, (const char*)(Wlo + (size_t)(n0 + r) * Ktot + kg) + q * 16);
        }
        cp_commit();
    };

    prefetch(0, 0);

    for (int c = 0; c < nch; c++) {
        if (c + 1 < nch) { prefetch(c + 1, (c + 1) & 1); cp_wait1(); }
        else             { cp_wait0(); }
        __syncthreads();

        uint32_t abase = sb + (c & 1) * STAGEB;
        uint32_t wbase = abase + TILEB;
#pragma unroll
        for (int kstep = 0; kstep < 4; kstep++) {
            uint32_t bhi[4][2], blo[4][2], afr[4][4];
            // W fragments: ldmatrix.x4 packs an n-tile pair (both k-halves)
#pragma unroll
            for (int np = 0; np < 2; np++) {
                uint32_t wa = wbase + (wn + np * 16 + ((lane >> 4) * 8) + (lane & 7)) * ROWB
                              + kstep * 32 + ((lane >> 3) & 1) * 16;
                uint32_t d[4];
                ldsm_x4(d, wa);
                bhi[np * 2][0] = d[0]; bhi[np * 2][1] = d[1];
                bhi[np * 2 + 1][0] = d[2]; bhi[np * 2 + 1][1] = d[3];
                ldsm_x4(d, wa + TILEB);
                blo[np * 2][0] = d[0]; blo[np * 2][1] = d[1];
                blo[np * 2 + 1][0] = d[2]; blo[np * 2 + 1][1] = d[3];
            }
#pragma unroll
            for (int mt = 0; mt < 4; mt++) {
                uint32_t aa = abase + (wm + mt * 16 + (lane & 15)) * ROWB
                              + kstep * 32 + (lane >> 4) * 16;
                ldsm_x4(afr[mt], aa);
            }
#pragma unroll
            for (int mt = 0; mt < 4; mt++)
#pragma unroll
                for (int nt = 0; nt < 4; nt++) mma16816(acc[mt][nt], afr[mt], bhi[nt]);
#pragma unroll
            for (int mt = 0; mt < 4; mt++)
#pragma unroll
                for (int nt = 0; nt < 4; nt++) mma16816(acc[mt][nt], afr[mt], blo[nt]);
        }
        __syncthreads();
    }

    // ---------------- epilogue (fast transcendentals) ----------------
    const int r0 = lane >> 2, cp2 = (lane & 3) * 2;
#pragma unroll
    for (int mt = 0; mt < 4; mt++) {
        int rl = m0 + wm + mt * 16 + r0;     // low row (high row = rl+8)
#pragma unroll
        for (int nt = 0; nt < 4; nt++) {
            float* v = acc[mt][nt];
            int c0 = n0 + wn + nt * 8 + cp2;
            float b0v = bias[c0], b1v = bias[c0 + 1];
            v[0] += b0v; v[1] += b1v; v[2] += b0v; v[3] += b1v;
            if (Ks > 0) {
                const float* xr0 = Xs + (size_t)rl * ldXs;
                const float* xr1 = Xs + (size_t)(rl + 8) * ldXs;
                const float* w0p = Wside + (size_t)c0 * Ks;
                const float* w1p = Wside + (size_t)(c0 + 1) * Ks;
#pragma unroll 4
                for (int k = 0; k < Ks; k++) {
                    float x0 = xr0[k], x1 = xr1[k];
                    float w0 = w0p[k], w1 = w1p[k];
                    v[0] += x0 * w0; v[1] += x0 * w1;
                    v[2] += x1 * w0; v[3] += x1 * w1;
                }
            }
            if (mode == 0) {
                // gate exchange across lane pair (bit0): even lane holds (i,f), odd (g,o)
                float e0 = __shfl_xor_sync(0xffffffffu, v[0], 1);
                float e1 = __shfl_xor_sync(0xffffffffu, v[1], 1);
                float e2 = __shfl_xor_sync(0xffffffffu, v[2], 1);
                float e3 = __shfl_xor_sync(0xffffffffu, v[3], 1);
                float zi, zf, zg, zo;
                int row;
                if ((lane & 1) == 0) { zi = v[0]; zf = v[1]; zg = e0; zo = e1; row = rl; }
                else                 { zi = e2;  zf = e3;  zg = v[2]; zo = v[3]; row = rl + 8; }
                int u = c0 >> 2;
                size_t ci = (size_t)row * Hv + u;
                float cc = sigf(zf) * cstate[ci] + sigf(zi) * tanhfast(zg);
                cstate[ci] = cc;
                float hv = sigf(zo) * tanhfast(cc);
                Hout[ci] = __float2half(hv);
            } else {
                float2 lo2 = make_float2(fmaxf(v[0], 0.f), fmaxf(v[1], 0.f));
                float2 hi2 = make_float2(fmaxf(v[2], 0.f), fmaxf(v[3], 0.f));
                *(float2*)&fout[(size_t)rl * ldout + c0]       = lo2;
                *(float2*)&fout[(size_t)(rl + 8) * ldout + c0] = hi2;
            }
        }
    }
}

// ======================= kernels wrapping the core =======================
// Fused encoder step, longest-job-first: z=0 -> layer1 (K=1024, step t-1);
// z=1 -> layer0 (K=512, step t). Long CTAs get low block IDs -> scheduled first.
__global__ __launch_bounds__(256, 2) void enc_fused(
    const __half* __restrict__ h0in, const __half* __restrict__ W0hi,
    const __half* __restrict__ W0lo, const float* __restrict__ b0p,
    const float* __restrict__ xt, const float* __restrict__ Ws0,
    float* __restrict__ c0, __half* __restrict__ h0out,
    const __half* __restrict__ h1in, const __half* __restrict__ W1hi,
    const __half* __restrict__ W1lo, const float* __restrict__ b1p,
    float* __restrict__ c1, __half* __restrict__ h1out, int do0, int do1)
{
    extern __shared__ char smem[];
    int m0 = blockIdx.y * 128, n0 = blockIdx.x * 128;
    if (blockIdx.z == 0) {
        if (!do1) return;
        core_gemm(smem, m0, n0, h0in, h1in, W1hi, W1lo, 2 * Hv, b1p,
                  (const float*)0, 0, (const float*)0, 0, 0, c1, h1out, (float*)0, 0);
    } else {
        if (!do0) return;
        core_gemm(smem, m0, n0, h0in, (const __half*)0, W0hi, W0lo, Hv, b0p,
                  xt, Sv * Fv, Ws0, Fv, 0, c0, h0out, (float*)0, 0);
    }
}

// Decoder LSTM step
__global__ __launch_bounds__(256, 2) void dec_lstm(
    const __half* __restrict__ h1in, const __half* __restrict__ Wdhi,
    const __half* __restrict__ Wdlo, const float* __restrict__ bdp,
    const float* __restrict__ din, const float* __restrict__ Wsd,
    float* __restrict__ c1, __half* __restrict__ h1out)
{
    extern __shared__ char smem[];
    core_gemm(smem, blockIdx.y * 128, blockIdx.x * 128, h1in, (const __half*)0,
              Wdhi, Wdlo, Hv, bdp, din, 4, Wsd, 4, 0, c1, h1out, (float*)0, 0);
}

// Fused MoE: gating layer1 (2 n-tiles) + 3 expert layer1s (16 n-tiles each)
__global__ __launch_bounds__(256, 2) void moe_gemm(
    const __half* __restrict__ ctx,
    const __half* __restrict__ gWhi, const __half* __restrict__ gWlo,
    const float* __restrict__ gb1, float* __restrict__ ghid,
    const __half* __restrict__ tWhi, const __half* __restrict__ tWlo,
    const float* __restrict__ tb1, float* __restrict__ et,
    const __half* __restrict__ iWhi, const __half* __restrict__ iWlo,
    const float* __restrict__ ib1, float* __restrict__ ei,
    const __half* __restrict__ wWhi, const __half* __restrict__ wWlo,
    const float* __restrict__ wb1, float* __restrict__ ew)
{
    extern __shared__ char smem[];
    int j = blockIdx.x, m0 = blockIdx.y * 128;
    const __half *Whi, *Wlo;
    const float* bias;
    float* fo;
    int ld, n0;
    if (j < 2) { Whi = gWhi; Wlo = gWlo; bias = gb1; fo = ghid; ld = HHv; n0 = j * 128; }
    else {
        int e = (j - 2) >> 4, jj = (j - 2) & 15;
        n0 = jj * 128; ld = H4;
        if (e == 0)      { Whi = tWhi; Wlo = tWlo; bias = tb1; fo = et; }
        else if (e == 1) { Whi = iWhi; Wlo = iWlo; bias = ib1; fo = ei; }
        else             { Whi = wWhi; Wlo = wWlo; bias = wb1; fo = ew; }
    }
    core_gemm(smem, m0, n0, ctx, (const __half*)0, Whi, Wlo, Hv, bias,
              (const float*)0, 0, (const float*)0, 0, 1, (float*)0, (__half*)0, fo, ld);
}

// ======================= fused gating + expert-head combine (warp per row) =======================
__global__ void head_comb(const float* __restrict__ hdd,
                          const float* __restrict__ gW2, const float* __restrict__ gb2,
                          const float* __restrict__ et, const float* __restrict__ ei,
                          const float* __restrict__ ew,
                          const float* __restrict__ tW2, const float* __restrict__ tb2,
                          const float* __restrict__ iW2, const float* __restrict__ ib2,
                          const float* __restrict__ wW2, const float* __restrict__ wb2,
                          float* __restrict__ gacc,
                          float* __restrict__ out, float* __restrict__ din_next, int t)
{
    int warp = (blockIdx.x * blockDim.x + threadIdx.x) >> 5;
    int lane = threadIdx.x & 31;
    if (warp >= Bv) return;
    int b = warp;

    // ---- gating: logits + softmax (lane 0 holds g[e]) ----
    float ga[Ev];
#pragma unroll
    for (int e = 0; e < Ev; e++) ga[e] = 0.f;
    {
        const float* hr = hdd + (size_t)b * HHv;
        for (int k = lane; k < HHv; k += 32) {
            float hv = hr[k];
#pragma unroll
            for (int e = 0; e < Ev; e++) ga[e] += hv * gW2[e * HHv + k];
        }
#pragma unroll
        for (int e = 0; e < Ev; e++)
#pragma unroll
            for (int o = 16; o > 0; o >>= 1) ga[e] += __shfl_xor_sync(0xffffffffu, ga[e], o);
    }
    float g[Ev];
    if (lane == 0) {
        float m = -1e30f;
#pragma unroll
        for (int e = 0; e < Ev; e++) { g[e] = ga[e] + gb2[e]; m = fmaxf(m, g[e]); }
        float s = 0.f;
#pragma unroll
        for (int e = 0; e < Ev; e++) { g[e] = __expf(g[e] - m); s += g[e]; }
        float inv = 1.f / s;
#pragma unroll
        for (int e = 0; e < Ev; e++) {
            g[e] *= inv;
            gacc[b * Ev + e] += g[e];
        }
    }

    // ---- expert heads + gated combine ----
    float tr0 = 0.f, tr1 = 0.f, dw = 0.f, wd = 0.f;
#pragma unroll
    for (int e = 0; e < Ev; e++) {
        float s0 = 0.f, s1 = 0.f, s2 = 0.f, s3 = 0.f;
        const float* ht = et + (size_t)b * H4 + e * HHv;
        const float* hi = ei + (size_t)b * H4 + e * HHv;
        const float* hw = ew + (size_t)b * H4 + e * HHv;
        const float* t0 = tW2 + (e * 2 + 0) * HHv;
        const float* t1 = tW2 + (e * 2 + 1) * HHv;
        const float* i0 = iW2 + e * HHv;
        const float* w0 = wW2 + e * HHv;
        for (int k = lane; k < HHv; k += 32) {
            float a = ht[k], bb = hi[k], c = hw[k];
            s0 += a * t0[k]; s1 += a * t1[k]; s2 += bb * i0[k]; s3 += c * w0[k];
        }
#pragma unroll
        for (int o = 16; o > 0; o >>= 1) {
            s0 += __shfl_xor_sync(0xffffffffu, s0, o);
            s1 += __shfl_xor_sync(0xffffffffu, s1, o);
            s2 += __shfl_xor_sync(0xffffffffu, s2, o);
            s3 += __shfl_xor_sync(0xffffffffu, s3, o);
        }
        if (lane == 0) {
            tr0 += g[e] * (s0 + tb2[e * 2 + 0]);
            tr1 += g[e] * (s1 + tb2[e * 2 + 1]);
            dw  += g[e] * (s2 + ib2[e]);
            wd  += g[e] * (s3 + wb2[e]);
        }
    }
    if (lane == 0) {
        out[(size_t)b * 16 + t]     = tr0;
        out[(size_t)b * 16 + 8 + t] = tr1;
        out[(size_t)Bv * 16 + (size_t)b * 8 + t] = dw;
        out[(size_t)Bv * 24 + (size_t)b * 8 + t] = wd;
        float* dn = din_next + b * 4;
        dn[0] = tr0; dn[1] = tr1; dn[2] = dw; dn[3] = wd;
    }
}

__global__ void fin_k(const float* __restrict__ gacc, float* __restrict__ out)
{
    int i = blockIdx.x * blockDim.x + threadIdx.x;
    if (i < Bv * Ev) out[(size_t)Bv * 32 + i] = gacc[i] * (1.f / HOR);
}

// ======================= launch =======================
extern "C" void kernel_launch(void* const* d_in, const int* in_sizes, int n_in,
                              void* d_out, int out_size)
{
    const float* x        = (const float*)d_in[0];
    const float* enc_Wih0 = (const float*)d_in[1];
    const float* enc_Whh0 = (const float*)d_in[2];
    const float* enc_b0   = (const float*)d_in[3];
    const float* enc_Wih1 = (const float*)d_in[4];
    const float* enc_Whh1 = (const float*)d_in[5];
    const float* enc_b1   = (const float*)d_in[6];
    const float* dec_Wih  = (const float*)d_in[7];
    const float* dec_Whh  = (const float*)d_in[8];
    const float* dec_b    = (const float*)d_in[9];
    const float* gW1      = (const float*)d_in[10];
    const float* gb1      = (const float*)d_in[11];
    const float* gW2      = (const float*)d_in[12];
    const float* gb2      = (const float*)d_in[13];
    const float* tW1      = (const float*)d_in[14];
    const float* tb1      = (const float*)d_in[15];
    const float* tW2      = (const float*)d_in[16];
    const float* tb2      = (const float*)d_in[17];
    const float* iW1      = (const float*)d_in[18];
    const float* ib1      = (const float*)d_in[19];
    const float* iW2      = (const float*)d_in[20];
    const float* ib2      = (const float*)d_in[21];
    const float* wW1      = (const float*)d_in[22];
    const float* wb1      = (const float*)d_in[23];
    const float* wW2      = (const float*)d_in[24];
    const float* wb2      = (const float*)d_in[25];
    float* out = (float*)d_out;

    cudaFuncSetAttribute(enc_fused, cudaFuncAttributeMaxDynamicSharedMemorySize, SM_BYTES);
    cudaFuncSetAttribute(dec_lstm,  cudaFuncAttributeMaxDynamicSharedMemorySize, SM_BYTES);
    cudaFuncSetAttribute(moe_gemm,  cudaFuncAttributeMaxDynamicSharedMemorySize, SM_BYTES);

    __half *h0[2], *h1[2];
    __half *W0hi, *W0lo, *W1hi, *W1lo, *Wdhi, *Wdlo;
    __half *gWhi, *gWlo, *tWhi, *tWlo, *iWhi, *iWlo, *wWhi, *wWlo;
    float *c0, *c1, *ghid, *et, *ei, *ew, *gacc, *din, *b0p, *b1p, *bdp, *Ws0, *Wsd;
    {
        void* p;
        cudaGetSymbolAddress(&p, g_h0);   h0[0] = (__half*)p; h0[1] = h0[0] + BH;
        cudaGetSymbolAddress(&p, g_h1);   h1[0] = (__half*)p; h1[1] = h1[0] + BH;
        cudaGetSymbolAddress(&p, g_c0);   c0 = (float*)p;
        cudaGetSymbolAddress(&p, g_c1);   c1 = (float*)p;
        cudaGetSymbolAddress(&p, g_ghid); ghid = (float*)p;
        cudaGetSymbolAddress(&p, g_et);   et = (float*)p;
        cudaGetSymbolAddress(&p, g_ei);   ei = (float*)p;
        cudaGetSymbolAddress(&p, g_ew);   ew = (float*)p;
        cudaGetSymbolAddress(&p, g_gacc); gacc = (float*)p;
        cudaGetSymbolAddress(&p, g_din);  din = (float*)p;
        cudaGetSymbolAddress(&p, g_W0hi); W0hi = (__half*)p;
        cudaGetSymbolAddress(&p, g_W0lo); W0lo = (__half*)p;
        cudaGetSymbolAddress(&p, g_W1hi); W1hi = (__half*)p;
        cudaGetSymbolAddress(&p, g_W1lo); W1lo = (__half*)p;
        cudaGetSymbolAddress(&p, g_Wdhi); Wdhi = (__half*)p;
        cudaGetSymbolAddress(&p, g_Wdlo); Wdlo = (__half*)p;
        cudaGetSymbolAddress(&p, g_gWhi); gWhi = (__half*)p;
        cudaGetSymbolAddress(&p, g_gWlo); gWlo = (__half*)p;
        cudaGetSymbolAddress(&p, g_tWhi); tWhi = (__half*)p;
        cudaGetSymbolAddress(&p, g_tWlo); tWlo = (__half*)p;
        cudaGetSymbolAddress(&p, g_iWhi); iWhi = (__half*)p;
        cudaGetSymbolAddress(&p, g_iWlo); iWlo = (__half*)p;
        cudaGetSymbolAddress(&p, g_wWhi); wWhi = (__half*)p;
        cudaGetSymbolAddress(&p, g_wWlo); wWlo = (__half*)p;
        cudaGetSymbolAddress(&p, g_b0p);  b0p = (float*)p;
        cudaGetSymbolAddress(&p, g_b1p);  b1p = (float*)p;
        cudaGetSymbolAddress(&p, g_bdp);  bdp = (float*)p;
        cudaGetSymbolAddress(&p, g_Ws0);  Ws0 = (float*)p;
        cudaGetSymbolAddress(&p, g_Wsd);  Wsd = (float*)p;
    }

    // single fused prep + init launch
    prep_all<<<1024, 256>>>(enc_Wih0, enc_Whh0, enc_b0, enc_Wih1, enc_Whh1, enc_b1,
                            dec_Wih, dec_Whh, dec_b, gW1, tW1, iW1, wW1);

    int p0 = 0, p1 = 0, pd = 0;

    // ---- encoder: skew-pipelined, 65 fused launches ----
    for (int t = 0; t <= Sv; t++) {
        int do0 = (t < Sv) ? 1 : 0;
        int do1 = (t > 0) ? 1 : 0;
        const float* xt = x + (do0 ? t : 0) * Fv;
        enc_fused<<<dim3(16, 16, 2), 256, SM_BYTES>>>(
            h0[p0], W0hi, W0lo, b0p, xt, Ws0, c0, h0[p0 ^ 1],
            h1[p1], W1hi, W1lo, b1p, c1, h1[p1 ^ 1], do0, do1);
        if (do0) p0 ^= 1;
        if (do1) p1 ^= 1;
    }

    // ---- decoder: 8 steps, 3 launches each ----
    for (int t = 0; t < HOR; t++) {
        dec_lstm<<<dim3(16, 16), 256, SM_BYTES>>>(
            h1[p1], Wdhi, Wdlo, bdp, din + pd * Bv * 4, Wsd, c1, h1[p1 ^ 1]);
        p1 ^= 1;

        moe_gemm<<<dim3(50, 16), 256, SM_BYTES>>>(
            h1[p1],
            gWhi, gWlo, gb1, ghid,
            tWhi, tWlo, tb1, et,
            iWhi, iWlo, ib1, ei,
            wWhi, wWlo, wb1, ew);

        head_comb<<<Bv / 8, 256>>>(ghid, gW2, gb2, et, ei, ew,
                                   tW2, tb2, iW2, ib2, wW2, wb2,
                                   gacc, out, din + (pd ^ 1) * Bv * 4, t);
        pd ^= 1;
    }

    fin_k<<<(Bv * Ev + 255) / 256, 256>>>(gacc, out);
}

// round 16
// speedup vs baseline: 1.3143x; 1.0760x over previous
#include <cuda_runtime.h>
#include <cuda_fp16.h>
#include <math.h>
#include <stdint.h>

// Problem constants
#define Bv   2048
#define Sv   64
#define Fv   16
#define Hv   512
#define H4   2048
#define Ev   8
#define HHv  256
#define HOR  8
#define BH   (Bv*Hv)

// tile geometry (padded smem image, 144 B row pitch)
#define ROWB  144
#define TILEB (128 * ROWB)          // 18432 B  (128 rows x 64 halfs + pad)
#define TILEH (TILEB / 2)           // 9216 halfs
#define PAIRB (2 * TILEB)           // hi|lo weight pair, 36864 B
#define PAIRH (2 * TILEH)
#define STAGEB (3 * TILEB)          // A | Whi | Wlo
#define SM_BYTES (1024 + 2 * STAGEB)   // mbarriers + 2 stages = 111616 B
#define HT (16 * 8 * TILEH)         // one tiled h buffer (halfs)

// ======================= helpers =======================
__device__ __forceinline__ uint32_t smem_to_u32(const void* p) {
    uint32_t a;
    asm("{ .reg .u64 t; cvta.to.shared.u64 t, %1; cvt.u32.u64 %0, t; }" : "=r"(a) : "l"(p));
    return a;
}
__device__ __forceinline__ void mma16816(float* c, const uint32_t* a, const uint32_t* b) {
    asm volatile("mma.sync.aligned.m16n8k16.row.col.f32.f16.f16.f32 "
        "{%0,%1,%2,%3}, {%4,%5,%6,%7}, {%8,%9}, {%0,%1,%2,%3};"
        : "+f"(c[0]), "+f"(c[1]), "+f"(c[2]), "+f"(c[3])
        : "r"(a[0]), "r"(a[1]), "r"(a[2]), "r"(a[3]), "r"(b[0]), "r"(b[1]));
}
__device__ __forceinline__ void ldsm_x4(uint32_t* d, uint32_t addr) {
    asm volatile("ldmatrix.sync.aligned.m8n8.x4.shared.b16 {%0,%1,%2,%3}, [%4];"
        : "=r"(d[0]), "=r"(d[1]), "=r"(d[2]), "=r"(d[3]) : "r"(addr));
}
__device__ __forceinline__ void mbar_init(uint32_t mbar, uint32_t cnt) {
    asm volatile("mbarrier.init.shared.b64 [%0], %1;" :: "r"(mbar), "r"(cnt) : "memory");
}
__device__ __forceinline__ void mbar_expect(uint32_t mbar, uint32_t bytes) {
    asm volatile("mbarrier.arrive.expect_tx.shared.b64 _, [%0], %1;"
                 :: "r"(mbar), "r"(bytes) : "memory");
}
__device__ __forceinline__ void mbar_wait(uint32_t mbar, uint32_t parity) {
    uint32_t done;
    asm volatile("{\n\t.reg .pred p;\n\t"
        "mbarrier.try_wait.parity.acquire.cta.shared::cta.b64 p, [%1], %2;\n\t"
        "selp.b32 %0, 1, 0, p;\n\t}" : "=r"(done) : "r"(mbar), "r"(parity) : "memory");
    while (!done) {
        asm volatile("{\n\t.reg .pred p;\n\t"
            "mbarrier.try_wait.parity.acquire.cta.shared::cta.b64 p, [%1], %2, 0x989680;\n\t"
            "selp.b32 %0, 1, 0, p;\n\t}" : "=r"(done) : "r"(mbar), "r"(parity) : "memory");
    }
}
__device__ __forceinline__ void bulk_ld(uint32_t dst, const void* src, uint32_t bytes, uint32_t mbar) {
    asm volatile("cp.async.bulk.shared::cluster.global.mbarrier::complete_tx::bytes "
                 "[%0], [%1], %2, [%3];"
                 :: "r"(dst), "l"(src), "r"(bytes), "r"(mbar) : "memory");
}
__device__ __forceinline__ float sigf(float x)     { return 1.f / (1.f + __expf(-x)); }
__device__ __forceinline__ float tanhfast(float x) { return 1.f - 2.f / (__expf(2.f * x) + 1.f); }

// ======================= device scratch =======================
__device__ __half g_h0t[2][HT];      // tiled h0 (16 mblk x 8 kchunk tiles)
__device__ __half g_h1t[2][HT];      // tiled h1
__device__ float g_c0[BH], g_c1[BH];
__device__ float g_ghid[Bv * HHv];
__device__ float g_et[Bv * H4], g_ei[Bv * H4], g_ew[Bv * H4];
__device__ float g_gacc[Bv * Ev];
__device__ float g_din[2][Bv * 4];

// tiled weights: per (nblk, kchunk) a hi|lo pair of smem tile images
__device__ __half g_W0t[16 * 8 * PAIRH];
__device__ __half g_W1t[16 * 16 * PAIRH];
__device__ __half g_Wdt[16 * 8 * PAIRH];
__device__ __half g_gWt[2 * 8 * PAIRH];
__device__ __half g_tWt[16 * 8 * PAIRH];
__device__ __half g_iWt[16 * 8 * PAIRH];
__device__ __half g_wWt[16 * 8 * PAIRH];
__device__ float g_b0p[H4], g_b1p[H4], g_bdp[H4];
__device__ float g_Ws0[H4 * Fv];
__device__ float g_Wsd[H4 * 4];

// ======================= single fused prep + init kernel =======================
#define S_W0   (H4 * Hv)
#define S_W1   (H4 * 2 * Hv)
#define S_WD   (H4 * Hv)
#define S_GW   (HHv * Hv)
#define S_TW   (H4 * Hv)
#define S_WS0  (H4 * Fv)
#define S_WSD  (H4 * 4)
#define S_B    (H4)
#define S_INIT (HT)

__device__ __forceinline__ void w_tile(__half* base, int nkW, int n, int k, float v) {
    int nb = n >> 7, r = n & 127, kc = k >> 6, col = k & 63;
    size_t off = (size_t)(nb * nkW + kc) * PAIRH + (size_t)r * 72 + col;
    __half h = __float2half(v);
    base[off] = h;
    base[off + TILEH] = __float2half(v - __half2float(h));
}

__global__ void prep_all(const float* enc_Wih0, const float* enc_Whh0, const float* enc_b0,
                         const float* enc_Wih1, const float* enc_Whh1, const float* enc_b1,
                         const float* dec_Wih, const float* dec_Whh, const float* dec_b,
                         const float* gW1, const float* tW1, const float* iW1, const float* wW1)
{
    const long T0 = S_W0, T1 = T0 + S_W1, T2 = T1 + S_WD, T3 = T2 + S_GW;
    const long T4 = T3 + S_TW, T5 = T4 + S_TW, T6 = T5 + S_TW;
    const long T7 = T6 + S_WS0, T8 = T7 + S_WSD, T9 = T8 + 3 * S_B;
    const long TOTAL = T9 + S_INIT;
    for (long i = blockIdx.x * (long)blockDim.x + threadIdx.x; i < TOTAL;
         i += (long)gridDim.x * blockDim.x) {
        if (i < T0) {
            long j = i;
            int n = (int)(j / Hv), k = (int)(j % Hv);
            int orig = (n & 3) * Hv + (n >> 2);
            w_tile(g_W0t, 8, n, k, enc_Whh0[(long)orig * Hv + k]);
        } else if (i < T1) {
            long j = i - T0;
            int n = (int)(j / (2 * Hv)), k = (int)(j % (2 * Hv));
            int orig = (n & 3) * Hv + (n >> 2);
            float v = (k < Hv) ? enc_Wih1[(long)orig * Hv + k]
                               : enc_Whh1[(long)orig * Hv + (k - Hv)];
            w_tile(g_W1t, 16, n, k, v);
        } else if (i < T2) {
            long j = i - T1;
            int n = (int)(j / Hv), k = (int)(j % Hv);
            int orig = (n & 3) * Hv + (n >> 2);
            w_tile(g_Wdt, 8, n, k, dec_Whh[(long)orig * Hv + k]);
        } else if (i < T3) {
            long j = i - T2;
            int n = (int)(j / Hv), k = (int)(j % Hv);
            w_tile(g_gWt, 8, n, k, gW1[j]);
        } else if (i < T4) {
            long j = i - T3;
            int n = (int)(j / Hv), k = (int)(j % Hv);
            w_tile(g_tWt, 8, n, k, tW1[j]);
        } else if (i < T5) {
            long j = i - T4;
            int n = (int)(j / Hv), k = (int)(j % Hv);
            w_tile(g_iWt, 8, n, k, iW1[j]);
        } else if (i < T6) {
            long j = i - T5;
            int n = (int)(j / Hv), k = (int)(j % Hv);
            w_tile(g_wWt, 8, n, k, wW1[j]);
        } else if (i < T7) {
            long j = i - T6;
            int n = (int)(j / Fv), k = (int)(j % Fv);
            int orig = (n & 3) * Hv + (n >> 2);
            g_Ws0[j] = enc_Wih0[(long)orig * Fv + k];
        } else if (i < T8) {
            long j = i - T7;
            int n = (int)(j / 4), k = (int)(j % 4);
            int orig = (n & 3) * Hv + (n >> 2);
            g_Wsd[j] = dec_Wih[(long)orig * 4 + k];
        } else if (i < T9) {
            long j = i - T8;
            int which = (int)(j / S_B), n = (int)(j % S_B);
            int orig = (n & 3) * Hv + (n >> 2);
            if (which == 0)      g_b0p[n] = enc_b0[orig];
            else if (which == 1) g_b1p[n] = enc_b1[orig];
            else                 g_bdp[n] = dec_b[orig];
        } else {
            long j = i - T9;                 // j < HT
            g_h0t[0][j] = __float2half(0.f);
            g_h1t[0][j] = __float2half(0.f);
            if (j < BH) { g_c0[j] = 0.f; g_c1[j] = 0.f; }
            if (j < Bv * 4) g_din[0][j] = 0.f;
            if (j < Bv * Ev) g_gacc[j] = 0.f;
        }
    }
}

// ======================= unified HMMA GEMM core (bulk-copy fed) =======================
__device__ __forceinline__ void core_gemm(
    char* smem, int m0, int n0,
    const __half* __restrict__ A1t, const __half* __restrict__ A2t,
    const __half* __restrict__ Wt, int Ktot,
    const float* __restrict__ bias,
    const float* __restrict__ Xs, int ldXs, const float* __restrict__ Wside, int Ks,
    int mode, float* __restrict__ cstate, __half* __restrict__ Hout_t,
    float* __restrict__ fout, int ldout)
{
    const int tid = threadIdx.x;
    const int wid = tid >> 5, lane = tid & 31;
    const int wm = (wid & 1) * 64;
    const int wn = (wid >> 1) * 32;
    const uint32_t sb = smem_to_u32(smem);
    const int mblk = m0 >> 7, nblk = n0 >> 7;
    const int nch = Ktot / 64;

    if (tid == 0) { mbar_init(sb, 1); mbar_init(sb + 8, 1); }
    __syncthreads();

    float acc[4][4][4];
#pragma unroll
    for (int a = 0; a < 4; a++)
#pragma unroll
        for (int b = 0; b < 4; b++)
#pragma unroll
            for (int d = 0; d < 4; d++) acc[a][b][d] = 0.f;

    auto prefetch = [&](int c) {
        int st = c & 1;
        uint32_t stage = sb + 1024 + st * STAGEB;
        uint32_t mbar = sb + st * 8;
        mbar_expect(mbar, (uint32_t)(TILEB + PAIRB));
        const __half* at = (c < 8) ? (A1t + ((size_t)(mblk * 8 + c)) * TILEH)
                                   : (A2t + ((size_t)(mblk * 8 + (c - 8))) * TILEH);
        bulk_ld(stage, at, TILEB, mbar);
        const __half* wt = Wt + ((size_t)(nblk * nch + c)) * PAIRH;
        bulk_ld(stage + TILEB, wt, PAIRB, mbar);
    };

    if (tid == 0) prefetch(0);

    for (int c = 0; c < nch; c++) {
        if (tid == 0 && c + 1 < nch) prefetch(c + 1);
        mbar_wait(sb + (c & 1) * 8, (uint32_t)((c >> 1) & 1));

        uint32_t abase = sb + 1024 + (c & 1) * STAGEB;
        uint32_t wbase = abase + TILEB;
#pragma unroll
        for (int kstep = 0; kstep < 4; kstep++) {
            uint32_t bhi[4][2], blo[4][2], afr[4][4];
#pragma unroll
            for (int np = 0; np < 2; np++) {
                uint32_t wa = wbase + (wn + np * 16 + ((lane >> 4) * 8) + (lane & 7)) * ROWB
                              + kstep * 32 + ((lane >> 3) & 1) * 16;
                uint32_t d[4];
                ldsm_x4(d, wa);
                bhi[np * 2][0] = d[0]; bhi[np * 2][1] = d[1];
                bhi[np * 2 + 1][0] = d[2]; bhi[np * 2 + 1][1] = d[3];
                ldsm_x4(d, wa + TILEB);
                blo[np * 2][0] = d[0]; blo[np * 2][1] = d[1];
                blo[np * 2 + 1][0] = d[2]; blo[np * 2 + 1][1] = d[3];
            }
#pragma unroll
            for (int mt = 0; mt < 4; mt++) {
                uint32_t aa = abase + (wm + mt * 16 + (lane & 15)) * ROWB
                              + kstep * 32 + (lane >> 4) * 16;
                ldsm_x4(afr[mt], aa);
            }
#pragma unroll
            for (int mt = 0; mt < 4; mt++)
#pragma unroll
                for (int nt = 0; nt < 4; nt++) mma16816(acc[mt][nt], afr[mt], bhi[nt]);
#pragma unroll
            for (int mt = 0; mt < 4; mt++)
#pragma unroll
                for (int nt = 0; nt < 4; nt++) mma16816(acc[mt][nt], afr[mt], blo[nt]);
        }
        __syncthreads();
    }

    // ---------------- epilogue ----------------
    const int r0 = lane >> 2, cp2 = (lane & 3) * 2;
#pragma unroll
    for (int mt = 0; mt < 4; mt++) {
        int rl = m0 + wm + mt * 16 + r0;
#pragma unroll
        for (int nt = 0; nt < 4; nt++) {
            float* v = acc[mt][nt];
            int c0 = n0 + wn + nt * 8 + cp2;
            float b0v = bias[c0], b1v = bias[c0 + 1];
            v[0] += b0v; v[1] += b1v; v[2] += b0v; v[3] += b1v;
            if (Ks > 0) {
                const float* xr0 = Xs + (size_t)rl * ldXs;
                const float* xr1 = Xs + (size_t)(rl + 8) * ldXs;
                const float* w0p = Wside + (size_t)c0 * Ks;
                const float* w1p = Wside + (size_t)(c0 + 1) * Ks;
#pragma unroll 4
                for (int k = 0; k < Ks; k++) {
                    float x0 = xr0[k], x1 = xr1[k];
                    float w0 = w0p[k], w1 = w1p[k];
                    v[0] += x0 * w0; v[1] += x0 * w1;
                    v[2] += x1 * w0; v[3] += x1 * w1;
                }
            }
            if (mode == 0) {
                float e0 = __shfl_xor_sync(0xffffffffu, v[0], 1);
                float e1 = __shfl_xor_sync(0xffffffffu, v[1], 1);
                float e2 = __shfl_xor_sync(0xffffffffu, v[2], 1);
                float e3 = __shfl_xor_sync(0xffffffffu, v[3], 1);
                float zi, zf, zg, zo;
                int row;
                if ((lane & 1) == 0) { zi = v[0]; zf = v[1]; zg = e0; zo = e1; row = rl; }
                else                 { zi = e2;  zf = e3;  zg = v[2]; zo = v[3]; row = rl + 8; }
                int u = c0 >> 2;
                size_t ci = (size_t)row * Hv + u;
                float cc = sigf(zf) * cstate[ci] + sigf(zi) * tanhfast(zg);
                cstate[ci] = cc;
                float hv = sigf(zo) * tanhfast(cc);
                size_t hidx = ((size_t)((row >> 7) * 8 + (u >> 6))) * TILEH
                              + (size_t)(row & 127) * 72 + (u & 63);
                Hout_t[hidx] = __float2half(hv);
            } else {
                float2 lo2 = make_float2(fmaxf(v[0], 0.f), fmaxf(v[1], 0.f));
                float2 hi2 = make_float2(fmaxf(v[2], 0.f), fmaxf(v[3], 0.f));
                *(float2*)&fout[(size_t)rl * ldout + c0]       = lo2;
                *(float2*)&fout[(size_t)(rl + 8) * ldout + c0] = hi2;
            }
        }
    }
}

// ======================= kernels wrapping the core =======================
__global__ __launch_bounds__(256, 2) void enc_fused(
    const __half* __restrict__ h0in, const float* __restrict__ b0p,
    const float* __restrict__ xt, const float* __restrict__ Ws0,
    float* __restrict__ c0, __half* __restrict__ h0out,
    const __half* __restrict__ h1in, const float* __restrict__ b1p,
    float* __restrict__ c1, __half* __restrict__ h1out, int do0, int do1)
{
    extern __shared__ char smem[];
    int m0 = blockIdx.y * 128, n0 = blockIdx.x * 128;
    if (blockIdx.z == 0) {
        if (!do1) return;
        core_gemm(smem, m0, n0, h0in, h1in, g_W1t, 2 * Hv, b1p,
                  (const float*)0, 0, (const float*)0, 0, 0, c1, h1out, (float*)0, 0);
    } else {
        if (!do0) return;
        core_gemm(smem, m0, n0, h0in, (const __half*)0, g_W0t, Hv, b0p,
                  xt, Sv * Fv, Ws0, Fv, 0, c0, h0out, (float*)0, 0);
    }
}

__global__ __launch_bounds__(256, 2) void dec_lstm(
    const __half* __restrict__ h1in, const float* __restrict__ bdp,
    const float* __restrict__ din, const float* __restrict__ Wsd,
    float* __restrict__ c1, __half* __restrict__ h1out)
{
    extern __shared__ char smem[];
    core_gemm(smem, blockIdx.y * 128, blockIdx.x * 128, h1in, (const __half*)0,
              g_Wdt, Hv, bdp, din, 4, Wsd, 4, 0, c1, h1out, (float*)0, 0);
}

__global__ __launch_bounds__(256, 2) void moe_gemm(
    const __half* __restrict__ ctx,
    const float* __restrict__ gb1, float* __restrict__ ghid,
    const float* __restrict__ tb1, float* __restrict__ et,
    const float* __restrict__ ib1, float* __restrict__ ei,
    const float* __restrict__ wb1, float* __restrict__ ew)
{
    extern __shared__ char smem[];
    int j = blockIdx.x, m0 = blockIdx.y * 128;
    const __half* Wt;
    const float* bias;
    float* fo;
    int ld, n0;
    if (j < 2) { Wt = g_gWt; bias = gb1; fo = ghid; ld = HHv; n0 = j * 128; }
    else {
        int e = (j - 2) >> 4, jj = (j - 2) & 15;
        n0 = jj * 128; ld = H4;
        if (e == 0)      { Wt = g_tWt; bias = tb1; fo = et; }
        else if (e == 1) { Wt = g_iWt; bias = ib1; fo = ei; }
        else             { Wt = g_wWt; bias = wb1; fo = ew; }
    }
    core_gemm(smem, m0, n0, ctx, (const __half*)0, Wt, Hv, bias,
              (const float*)0, 0, (const float*)0, 0, 1, (float*)0, (__half*)0, fo, ld);
}

// ======================= fused gating + expert-head combine =======================
__global__ void head_comb(const float* __restrict__ hdd,
                          const float* __restrict__ gW2, const float* __restrict__ gb2,
                          const float* __restrict__ et, const float* __restrict__ ei,
                          const float* __restrict__ ew,
                          const float* __restrict__ tW2, const float* __restrict__ tb2,
                          const float* __restrict__ iW2, const float* __restrict__ ib2,
                          const float* __restrict__ wW2, const float* __restrict__ wb2,
                          float* __restrict__ gacc,
                          float* __restrict__ out, float* __restrict__ din_next, int t)
{
    int warp = (blockIdx.x * blockDim.x + threadIdx.x) >> 5;
    int lane = threadIdx.x & 31;
    if (warp >= Bv) return;
    int b = warp;

    float ga[Ev];
#pragma unroll
    for (int e = 0; e < Ev; e++) ga[e] = 0.f;
    {
        const float* hr = hdd + (size_t)b * HHv;
        for (int k = lane; k < HHv; k += 32) {
            float hv = hr[k];
#pragma unroll
            for (int e = 0; e < Ev; e++) ga[e] += hv * gW2[e * HHv + k];
        }
#pragma unroll
        for (int e = 0; e < Ev; e++)
#pragma unroll
            for (int o = 16; o > 0; o >>= 1) ga[e] += __shfl_xor_sync(0xffffffffu, ga[e], o);
    }
    float g[Ev];
    if (lane == 0) {
        float m = -1e30f;
#pragma unroll
        for (int e = 0; e < Ev; e++) { g[e] = ga[e] + gb2[e]; m = fmaxf(m, g[e]); }
        float s = 0.f;
#pragma unroll
        for (int e = 0; e < Ev; e++) { g[e] = __expf(g[e] - m); s += g[e]; }
        float inv = 1.f / s;
#pragma unroll
        for (int e = 0; e < Ev; e++) {
            g[e] *= inv;
            gacc[b * Ev + e] += g[e];
        }
    }

    float tr0 = 0.f, tr1 = 0.f, dw = 0.f, wd = 0.f;
#pragma unroll
    for (int e = 0; e < Ev; e++) {
        float s0 = 0.f, s1 = 0.f, s2 = 0.f, s3 = 0.f;
        const float* ht = et + (size_t)b * H4 + e * HHv;
        const float* hi = ei + (size_t)b * H4 + e * HHv;
        const float* hw = ew + (size_t)b * H4 + e * HHv;
        const float* t0 = tW2 + (e * 2 + 0) * HHv;
        const float* t1 = tW2 + (e * 2 + 1) * HHv;
        const float* i0 = iW2 + e * HHv;
        const float* w0 = wW2 + e * HHv;
        for (int k = lane; k < HHv; k += 32) {
            float a = ht[k], bb = hi[k], c = hw[k];
            s0 += a * t0[k]; s1 += a * t1[k]; s2 += bb * i0[k]; s3 += c * w0[k];
        }
#pragma unroll
        for (int o = 16; o > 0; o >>= 1) {
            s0 += __shfl_xor_sync(0xffffffffu, s0, o);
            s1 += __shfl_xor_sync(0xffffffffu, s1, o);
            s2 += __shfl_xor_sync(0xffffffffu, s2, o);
            s3 += __shfl_xor_sync(0xffffffffu, s3, o);
        }
        if (lane == 0) {
            tr0 += g[e] * (s0 + tb2[e * 2 + 0]);
            tr1 += g[e] * (s1 + tb2[e * 2 + 1]);
            dw  += g[e] * (s2 + ib2[e]);
            wd  += g[e] * (s3 + wb2[e]);
        }
    }
    if (lane == 0) {
        out[(size_t)b * 16 + t]     = tr0;
        out[(size_t)b * 16 + 8 + t] = tr1;
        out[(size_t)Bv * 16 + (size_t)b * 8 + t] = dw;
        out[(size_t)Bv * 24 + (size_t)b * 8 + t] = wd;
        float* dn = din_next + b * 4;
        dn[0] = tr0; dn[1] = tr1; dn[2] = dw; dn[3] = wd;
    }
}

__global__ void fin_k(const float* __restrict__ gacc, float* __restrict__ out)
{
    int i = blockIdx.x * blockDim.x + threadIdx.x;
    if (i < Bv * Ev) out[(size_t)Bv * 32 + i] = gacc[i] * (1.f / HOR);
}

// ======================= launch =======================
extern "C" void kernel_launch(void* const* d_in, const int* in_sizes, int n_in,
                              void* d_out, int out_size)
{
    const float* x        = (const float*)d_in[0];
    const float* enc_Wih0 = (const float*)d_in[1];
    const float* enc_Whh0 = (const float*)d_in[2];
    const float* enc_b0   = (const float*)d_in[3];
    const float* enc_Wih1 = (const float*)d_in[4];
    const float* enc_Whh1 = (const float*)d_in[5];
    const float* enc_b1   = (const float*)d_in[6];
    const float* dec_Wih  = (const float*)d_in[7];
    const float* dec_Whh  = (const float*)d_in[8];
    const float* dec_b    = (const float*)d_in[9];
    const float* gW1      = (const float*)d_in[10];
    const float* gb1      = (const float*)d_in[11];
    const float* gW2      = (const float*)d_in[12];
    const float* gb2      = (const float*)d_in[13];
    const float* tW1      = (const float*)d_in[14];
    const float* tb1      = (const float*)d_in[15];
    const float* tW2      = (const float*)d_in[16];
    const float* tb2      = (const float*)d_in[17];
    const float* iW1      = (const float*)d_in[18];
    const float* ib1      = (const float*)d_in[19];
    const float* iW2      = (const float*)d_in[20];
    const float* ib2      = (const float*)d_in[21];
    const float* wW1      = (const float*)d_in[22];
    const float* wb1      = (const float*)d_in[23];
    const float* wW2      = (const float*)d_in[24];
    const float* wb2      = (const float*)d_in[25];
    float* out = (float*)d_out;

    cudaFuncSetAttribute(enc_fused, cudaFuncAttributeMaxDynamicSharedMemorySize, SM_BYTES);
    cudaFuncSetAttribute(dec_lstm,  cudaFuncAttributeMaxDynamicSharedMemorySize, SM_BYTES);
    cudaFuncSetAttribute(moe_gemm,  cudaFuncAttributeMaxDynamicSharedMemorySize, SM_BYTES);

    __half *h0t[2], *h1t[2];
    float *c0, *c1, *ghid, *et, *ei, *ew, *gacc, *din, *b0p, *b1p, *bdp, *Ws0, *Wsd;
    {
        void* p;
        cudaGetSymbolAddress(&p, g_h0t);  h0t[0] = (__half*)p; h0t[1] = h0t[0] + HT;
        cudaGetSymbolAddress(&p, g_h1t);  h1t[0] = (__half*)p; h1t[1] = h1t[0] + HT;
        cudaGetSymbolAddress(&p, g_c0);   c0 = (float*)p;
        cudaGetSymbolAddress(&p, g_c1);   c1 = (float*)p;
        cudaGetSymbolAddress(&p, g_ghid); ghid = (float*)p;
        cudaGetSymbolAddress(&p, g_et);   et = (float*)p;
        cudaGetSymbolAddress(&p, g_ei);   ei = (float*)p;
        cudaGetSymbolAddress(&p, g_ew);   ew = (float*)p;
        cudaGetSymbolAddress(&p, g_gacc); gacc = (float*)p;
        cudaGetSymbolAddress(&p, g_din);  din = (float*)p;
        cudaGetSymbolAddress(&p, g_b0p);  b0p = (float*)p;
        cudaGetSymbolAddress(&p, g_b1p);  b1p = (float*)p;
        cudaGetSymbolAddress(&p, g_bdp);  bdp = (float*)p;
        cudaGetSymbolAddress(&p, g_Ws0);  Ws0 = (float*)p;
        cudaGetSymbolAddress(&p, g_Wsd);  Wsd = (float*)p;
    }

    prep_all<<<1024, 256>>>(enc_Wih0, enc_Whh0, enc_b0, enc_Wih1, enc_Whh1, enc_b1,
                            dec_Wih, dec_Whh, dec_b, gW1, tW1, iW1, wW1);

    int p0 = 0, p1 = 0, pd = 0;

    // ---- encoder: skew-pipelined, 65 fused launches ----
    for (int t = 0; t <= Sv; t++) {
        int do0 = (t < Sv) ? 1 : 0;
        int do1 = (t > 0) ? 1 : 0;
        const float* xt = x + (do0 ? t : 0) * Fv;
        enc_fused<<<dim3(16, 16, 2), 256, SM_BYTES>>>(
            h0t[p0], b0p, xt, Ws0, c0, h0t[p0 ^ 1],
            h1t[p1], b1p, c1, h1t[p1 ^ 1], do0, do1);
        if (do0) p0 ^= 1;
        if (do1) p1 ^= 1;
    }

    // ---- decoder: 8 steps ----
    for (int t = 0; t < HOR; t++) {
        dec_lstm<<<dim3(16, 16), 256, SM_BYTES>>>(
            h1t[p1], bdp, din + pd * Bv * 4, Wsd, c1, h1t[p1 ^ 1]);
        p1 ^= 1;

        moe_gemm<<<dim3(50, 16), 256, SM_BYTES>>>(
            h1t[p1], gb1, ghid, tb1, et, ib1, ei, wb1, ew);

        head_comb<<<Bv / 8, 256>>>(ghid, gW2, gb2, et, ei, ew,
                                   tW2, tb2, iW2, ib2, wW2, wb2,
                                   gacc, out, din + (pd ^ 1) * Bv * 4, t);
        pd ^= 1;
    }

    fin_k<<<(Bv * Ev + 255) / 256, 256>>>(gacc, out);
}

// round 17
// speedup vs baseline: 1.6234x; 1.2352x over previous
#include <cuda_runtime.h>
#include <cuda_fp16.h>
#include <math.h>
#include <stdint.h>

// Problem constants
#define Bv   2048
#define Sv   64
#define Fv   16
#define Hv   512
#define H4   2048
#define Ev   8
#define HHv  256
#define HOR  8
#define BH   (Bv*Hv)

// tile geometry (padded smem image, 144 B row pitch)
#define ROWB  144
#define TILEB (128 * ROWB)          // 18432 B  (128 rows x 64 halfs + pad)
#define TILEH (TILEB / 2)           // 9216 halfs
#define NSTAGE 3
#define STAGEB (2 * TILEB)          // A | W  (36864 B)
#define SM_BYTES (1024 + NSTAGE * STAGEB)   // 111616 B
#define HT (16 * 8 * TILEH)         // one tiled h buffer (halfs)

// ======================= helpers =======================
__device__ __forceinline__ uint32_t smem_to_u32(const void* p) {
    uint32_t a;
    asm("{ .reg .u64 t; cvta.to.shared.u64 t, %1; cvt.u32.u64 %0, t; }" : "=r"(a) : "l"(p));
    return a;
}
__device__ __forceinline__ void mma16816(float* c, const uint32_t* a, const uint32_t* b) {
    asm volatile("mma.sync.aligned.m16n8k16.row.col.f32.f16.f16.f32 "
        "{%0,%1,%2,%3}, {%4,%5,%6,%7}, {%8,%9}, {%0,%1,%2,%3};"
        : "+f"(c[0]), "+f"(c[1]), "+f"(c[2]), "+f"(c[3])
        : "r"(a[0]), "r"(a[1]), "r"(a[2]), "r"(a[3]), "r"(b[0]), "r"(b[1]));
}
__device__ __forceinline__ void ldsm_x4(uint32_t* d, uint32_t addr) {
    asm volatile("ldmatrix.sync.aligned.m8n8.x4.shared.b16 {%0,%1,%2,%3}, [%4];"
        : "=r"(d[0]), "=r"(d[1]), "=r"(d[2]), "=r"(d[3]) : "r"(addr));
}
__device__ __forceinline__ void mbar_init(uint32_t mbar, uint32_t cnt) {
    asm volatile("mbarrier.init.shared.b64 [%0], %1;" :: "r"(mbar), "r"(cnt) : "memory");
}
__device__ __forceinline__ void mbar_expect(uint32_t mbar, uint32_t bytes) {
    asm volatile("mbarrier.arrive.expect_tx.shared.b64 _, [%0], %1;"
                 :: "r"(mbar), "r"(bytes) : "memory");
}
__device__ __forceinline__ void mbar_wait(uint32_t mbar, uint32_t parity) {
    uint32_t done;
    asm volatile("{\n\t.reg .pred p;\n\t"
        "mbarrier.try_wait.parity.acquire.cta.shared::cta.b64 p, [%1], %2;\n\t"
        "selp.b32 %0, 1, 0, p;\n\t}" : "=r"(done) : "r"(mbar), "r"(parity) : "memory");
    while (!done) {
        asm volatile("{\n\t.reg .pred p;\n\t"
            "mbarrier.try_wait.parity.acquire.cta.shared::cta.b64 p, [%1], %2, 0x989680;\n\t"
            "selp.b32 %0, 1, 0, p;\n\t}" : "=r"(done) : "r"(mbar), "r"(parity) : "memory");
    }
}
__device__ __forceinline__ void bulk_ld(uint32_t dst, const void* src, uint32_t bytes, uint32_t mbar) {
    asm volatile("cp.async.bulk.shared::cluster.global.mbarrier::complete_tx::bytes "
                 "[%0], [%1], %2, [%3];"
                 :: "r"(dst), "l"(src), "r"(bytes), "r"(mbar) : "memory");
}
__device__ __forceinline__ float sigf(float x)     { return 1.f / (1.f + __expf(-x)); }
__device__ __forceinline__ float tanhfast(float x) { return 1.f - 2.f / (__expf(2.f * x) + 1.f); }

// ======================= device scratch =======================
__device__ __half g_h0t[2][HT];      // tiled h0 (16 mblk x 8 kchunk tiles)
__device__ __half g_h1t[2][HT];      // tiled h1
__device__ float g_c0[BH], g_c1[BH];
__device__ float g_ghid[Bv * HHv];
__device__ float g_et[Bv * H4], g_ei[Bv * H4], g_ew[Bv * H4];
__device__ float g_gacc[Bv * Ev];
__device__ float g_din[2][Bv * 4];

// tiled weights: per (nblk, kchunk) one fp16 tile image
__device__ __half g_W0t[16 * 8 * TILEH];
__device__ __half g_W1t[16 * 16 * TILEH];
__device__ __half g_Wdt[16 * 8 * TILEH];
__device__ __half g_gWt[2 * 8 * TILEH];
__device__ __half g_tWt[16 * 8 * TILEH];
__device__ __half g_iWt[16 * 8 * TILEH];
__device__ __half g_wWt[16 * 8 * TILEH];
__device__ float g_b0p[H4], g_b1p[H4], g_bdp[H4];
__device__ float g_Ws0[H4 * Fv];
__device__ float g_Wsd[H4 * 4];

// ======================= single fused prep + init kernel =======================
#define S_W0   (H4 * Hv)
#define S_W1   (H4 * 2 * Hv)
#define S_WD   (H4 * Hv)
#define S_GW   (HHv * Hv)
#define S_TW   (H4 * Hv)
#define S_WS0  (H4 * Fv)
#define S_WSD  (H4 * 4)
#define S_B    (H4)
#define S_INIT (HT)

__device__ __forceinline__ void w_tile(__half* base, int nkW, int n, int k, float v) {
    int nb = n >> 7, r = n & 127, kc = k >> 6, col = k & 63;
    size_t off = (size_t)(nb * nkW + kc) * TILEH + (size_t)r * 72 + col;
    base[off] = __float2half(v);
}

__global__ void prep_all(const float* enc_Wih0, const float* enc_Whh0, const float* enc_b0,
                         const float* enc_Wih1, const float* enc_Whh1, const float* enc_b1,
                         const float* dec_Wih, const float* dec_Whh, const float* dec_b,
                         const float* gW1, const float* tW1, const float* iW1, const float* wW1)
{
    const long T0 = S_W0, T1 = T0 + S_W1, T2 = T1 + S_WD, T3 = T2 + S_GW;
    const long T4 = T3 + S_TW, T5 = T4 + S_TW, T6 = T5 + S_TW;
    const long T7 = T6 + S_WS0, T8 = T7 + S_WSD, T9 = T8 + 3 * S_B;
    const long TOTAL = T9 + S_INIT;
    for (long i = blockIdx.x * (long)blockDim.x + threadIdx.x; i < TOTAL;
         i += (long)gridDim.x * blockDim.x) {
        if (i < T0) {
            long j = i;
            int n = (int)(j / Hv), k = (int)(j % Hv);
            int orig = (n & 3) * Hv + (n >> 2);
            w_tile(g_W0t, 8, n, k, enc_Whh0[(long)orig * Hv + k]);
        } else if (i < T1) {
            long j = i - T0;
            int n = (int)(j / (2 * Hv)), k = (int)(j % (2 * Hv));
            int orig = (n & 3) * Hv + (n >> 2);
            float v = (k < Hv) ? enc_Wih1[(long)orig * Hv + k]
                               : enc_Whh1[(long)orig * Hv + (k - Hv)];
            w_tile(g_W1t, 16, n, k, v);
        } else if (i < T2) {
            long j = i - T1;
            int n = (int)(j / Hv), k = (int)(j % Hv);
            int orig = (n & 3) * Hv + (n >> 2);
            w_tile(g_Wdt, 8, n, k, dec_Whh[(long)orig * Hv + k]);
        } else if (i < T3) {
            long j = i - T2;
            int n = (int)(j / Hv), k = (int)(j % Hv);
            w_tile(g_gWt, 8, n, k, gW1[j]);
        } else if (i < T4) {
            long j = i - T3;
            int n = (int)(j / Hv), k = (int)(j % Hv);
            w_tile(g_tWt, 8, n, k, tW1[j]);
        } else if (i < T5) {
            long j = i - T4;
            int n = (int)(j / Hv), k = (int)(j % Hv);
            w_tile(g_iWt, 8, n, k, iW1[j]);
        } else if (i < T6) {
            long j = i - T5;
            int n = (int)(j / Hv), k = (int)(j % Hv);
            w_tile(g_wWt, 8, n, k, wW1[j]);
        } else if (i < T7) {
            long j = i - T6;
            int n = (int)(j / Fv), k = (int)(j % Fv);
            int orig = (n & 3) * Hv + (n >> 2);
            g_Ws0[j] = enc_Wih0[(long)orig * Fv + k];
        } else if (i < T8) {
            long j = i - T7;
            int n = (int)(j / 4), k = (int)(j % 4);
            int orig = (n & 3) * Hv + (n >> 2);
            g_Wsd[j] = dec_Wih[(long)orig * 4 + k];
        } else if (i < T9) {
            long j = i - T8;
            int which = (int)(j / S_B), n = (int)(j % S_B);
            int orig = (n & 3) * Hv + (n >> 2);
            if (which == 0)      g_b0p[n] = enc_b0[orig];
            else if (which == 1) g_b1p[n] = enc_b1[orig];
            else                 g_bdp[n] = dec_b[orig];
        } else {
            long j = i - T9;                 // j < HT
            g_h0t[0][j] = __float2half(0.f);
            g_h1t[0][j] = __float2half(0.f);
            if (j < BH) { g_c0[j] = 0.f; g_c1[j] = 0.f; }
            if (j < Bv * 4) g_din[0][j] = 0.f;
            if (j < Bv * Ev) g_gacc[j] = 0.f;
        }
    }
}

// ======================= unified HMMA GEMM core (bulk-fed, single W pass, 3-stage) =======================
__device__ __forceinline__ void core_gemm(
    char* smem, int m0, int n0,
    const __half* __restrict__ A1t, const __half* __restrict__ A2t,
    const __half* __restrict__ Wt, int Ktot,
    const float* __restrict__ bias,
    const float* __restrict__ Xs, int ldXs, const float* __restrict__ Wside, int Ks,
    int mode, float* __restrict__ cstate, __half* __restrict__ Hout_t,
    float* __restrict__ fout, int ldout)
{
    const int tid = threadIdx.x;
    const int wid = tid >> 5, lane = tid & 31;
    const int wm = (wid & 1) * 64;
    const int wn = (wid >> 1) * 32;
    const uint32_t sb = smem_to_u32(smem);
    const int mblk = m0 >> 7, nblk = n0 >> 7;
    const int nch = Ktot / 64;

    if (tid == 0) { mbar_init(sb, 1); mbar_init(sb + 8, 1); mbar_init(sb + 16, 1); }
    __syncthreads();

    float acc[4][4][4];
#pragma unroll
    for (int a = 0; a < 4; a++)
#pragma unroll
        for (int b = 0; b < 4; b++)
#pragma unroll
            for (int d = 0; d < 4; d++) acc[a][b][d] = 0.f;

    auto prefetch = [&](int c) {
        int st = c % NSTAGE;
        uint32_t stage = sb + 1024 + st * STAGEB;
        uint32_t mbar = sb + st * 8;
        mbar_expect(mbar, (uint32_t)(2 * TILEB));
        const __half* at = (c < 8) ? (A1t + ((size_t)(mblk * 8 + c)) * TILEH)
                                   : (A2t + ((size_t)(mblk * 8 + (c - 8))) * TILEH);
        bulk_ld(stage, at, TILEB, mbar);
        const __half* wt = Wt + ((size_t)(nblk * nch + c)) * TILEH;
        bulk_ld(stage + TILEB, wt, TILEB, mbar);
    };

    if (tid == 0) { prefetch(0); if (nch > 1) prefetch(1); }

    for (int c = 0; c < nch; c++) {
        if (tid == 0 && c + 2 < nch) prefetch(c + 2);
        mbar_wait(sb + (c % NSTAGE) * 8, (uint32_t)((c / NSTAGE) & 1));

        uint32_t abase = sb + 1024 + (c % NSTAGE) * STAGEB;
        uint32_t wbase = abase + TILEB;
#pragma unroll
        for (int kstep = 0; kstep < 4; kstep++) {
            uint32_t bhi[4][2], afr[4][4];
#pragma unroll
            for (int np = 0; np < 2; np++) {
                uint32_t wa = wbase + (wn + np * 16 + ((lane >> 4) * 8) + (lane & 7)) * ROWB
                              + kstep * 32 + ((lane >> 3) & 1) * 16;
                uint32_t d[4];
                ldsm_x4(d, wa);
                bhi[np * 2][0] = d[0]; bhi[np * 2][1] = d[1];
                bhi[np * 2 + 1][0] = d[2]; bhi[np * 2 + 1][1] = d[3];
            }
#pragma unroll
            for (int mt = 0; mt < 4; mt++) {
                uint32_t aa = abase + (wm + mt * 16 + (lane & 15)) * ROWB
                              + kstep * 32 + (lane >> 4) * 16;
                ldsm_x4(afr[mt], aa);
            }
#pragma unroll
            for (int mt = 0; mt < 4; mt++)
#pragma unroll
                for (int nt = 0; nt < 4; nt++) mma16816(acc[mt][nt], afr[mt], bhi[nt]);
        }
        __syncthreads();
    }

    // ---------------- epilogue ----------------
    const int r0 = lane >> 2, cp2 = (lane & 3) * 2;
#pragma unroll
    for (int mt = 0; mt < 4; mt++) {
        int rl = m0 + wm + mt * 16 + r0;
#pragma unroll
        for (int nt = 0; nt < 4; nt++) {
            float* v = acc[mt][nt];
            int c0 = n0 + wn + nt * 8 + cp2;
            float b0v = bias[c0], b1v = bias[c0 + 1];
            v[0] += b0v; v[1] += b1v; v[2] += b0v; v[3] += b1v;
            if (Ks > 0) {
                const float* xr0 = Xs + (size_t)rl * ldXs;
                const float* xr1 = Xs + (size_t)(rl + 8) * ldXs;
                const float* w0p = Wside + (size_t)c0 * Ks;
                const float* w1p = Wside + (size_t)(c0 + 1) * Ks;
#pragma unroll 4
                for (int k = 0; k < Ks; k++) {
                    float x0 = xr0[k], x1 = xr1[k];
                    float w0 = w0p[k], w1 = w1p[k];
                    v[0] += x0 * w0; v[1] += x0 * w1;
                    v[2] += x1 * w0; v[3] += x1 * w1;
                }
            }
            if (mode == 0) {
                float e0 = __shfl_xor_sync(0xffffffffu, v[0], 1);
                float e1 = __shfl_xor_sync(0xffffffffu, v[1], 1);
                float e2 = __shfl_xor_sync(0xffffffffu, v[2], 1);
                float e3 = __shfl_xor_sync(0xffffffffu, v[3], 1);
                float zi, zf, zg, zo;
                int row;
                if ((lane & 1) == 0) { zi = v[0]; zf = v[1]; zg = e0; zo = e1; row = rl; }
                else                 { zi = e2;  zf = e3;  zg = v[2]; zo = v[3]; row = rl + 8; }
                int u = c0 >> 2;
                size_t ci = (size_t)row * Hv + u;
                float cc = sigf(zf) * cstate[ci] + sigf(zi) * tanhfast(zg);
                cstate[ci] = cc;
                float hv = sigf(zo) * tanhfast(cc);
                size_t hidx = ((size_t)((row >> 7) * 8 + (u >> 6))) * TILEH
                              + (size_t)(row & 127) * 72 + (u & 63);
                Hout_t[hidx] = __float2half(hv);
            } else {
                float2 lo2 = make_float2(fmaxf(v[0], 0.f), fmaxf(v[1], 0.f));
                float2 hi2 = make_float2(fmaxf(v[2], 0.f), fmaxf(v[3], 0.f));
                *(float2*)&fout[(size_t)rl * ldout + c0]       = lo2;
                *(float2*)&fout[(size_t)(rl + 8) * ldout + c0] = hi2;
            }
        }
    }
}

// ======================= kernels wrapping the core =======================
__global__ __launch_bounds__(256, 2) void enc_fused(
    const __half* __restrict__ h0in, const float* __restrict__ b0p,
    const float* __restrict__ xt, const float* __restrict__ Ws0,
    float* __restrict__ c0, __half* __restrict__ h0out,
    const __half* __restrict__ h1in, const float* __restrict__ b1p,
    float* __restrict__ c1, __half* __restrict__ h1out, int do0, int do1)
{
    extern __shared__ char smem[];
    int m0 = blockIdx.y * 128, n0 = blockIdx.x * 128;
    if (blockIdx.z == 0) {
        if (!do1) return;
        core_gemm(smem, m0, n0, h0in, h1in, g_W1t, 2 * Hv, b1p,
                  (const float*)0, 0, (const float*)0, 0, 0, c1, h1out, (float*)0, 0);
    } else {
        if (!do0) return;
        core_gemm(smem, m0, n0, h0in, (const __half*)0, g_W0t, Hv, b0p,
                  xt, Sv * Fv, Ws0, Fv, 0, c0, h0out, (float*)0, 0);
    }
}

__global__ __launch_bounds__(256, 2) void dec_lstm(
    const __half* __restrict__ h1in, const float* __restrict__ bdp,
    const float* __restrict__ din, const float* __restrict__ Wsd,
    float* __restrict__ c1, __half* __restrict__ h1out)
{
    extern __shared__ char smem[];
    core_gemm(smem, blockIdx.y * 128, blockIdx.x * 128, h1in, (const __half*)0,
              g_Wdt, Hv, bdp, din, 4, Wsd, 4, 0, c1, h1out, (float*)0, 0);
}

__global__ __launch_bounds__(256, 2) void moe_gemm(
    const __half* __restrict__ ctx,
    const float* __restrict__ gb1, float* __restrict__ ghid,
    const float* __restrict__ tb1, float* __restrict__ et,
    const float* __restrict__ ib1, float* __restrict__ ei,
    const float* __restrict__ wb1, float* __restrict__ ew)
{
    extern __shared__ char smem[];
    int j = blockIdx.x, m0 = blockIdx.y * 128;
    const __half* Wt;
    const float* bias;
    float* fo;
    int ld, n0;
    if (j < 2) { Wt = g_gWt; bias = gb1; fo = ghid; ld = HHv; n0 = j * 128; }
    else {
        int e = (j - 2) >> 4, jj = (j - 2) & 15;
        n0 = jj * 128; ld = H4;
        if (e == 0)      { Wt = g_tWt; bias = tb1; fo = et; }
        else if (e == 1) { Wt = g_iWt; bias = ib1; fo = ei; }
        else             { Wt = g_wWt; bias = wb1; fo = ew; }
    }
    core_gemm(smem, m0, n0, ctx, (const __half*)0, Wt, Hv, bias,
              (const float*)0, 0, (const float*)0, 0, 1, (float*)0, (__half*)0, fo, ld);
}

// ======================= fused gating + expert-head combine =======================
__global__ void head_comb(const float* __restrict__ hdd,
                          const float* __restrict__ gW2, const float* __restrict__ gb2,
                          const float* __restrict__ et, const float* __restrict__ ei,
                          const float* __restrict__ ew,
                          const float* __restrict__ tW2, const float* __restrict__ tb2,
                          const float* __restrict__ iW2, const float* __restrict__ ib2,
                          const float* __restrict__ wW2, const float* __restrict__ wb2,
                          float* __restrict__ gacc,
                          float* __restrict__ out, float* __restrict__ din_next, int t)
{
    int warp = (blockIdx.x * blockDim.x + threadIdx.x) >> 5;
    int lane = threadIdx.x & 31;
    if (warp >= Bv) return;
    int b = warp;

    float ga[Ev];
#pragma unroll
    for (int e = 0; e < Ev; e++) ga[e] = 0.f;
    {
        const float* hr = hdd + (size_t)b * HHv;
        for (int k = lane; k < HHv; k += 32) {
            float hv = hr[k];
#pragma unroll
            for (int e = 0; e < Ev; e++) ga[e] += hv * gW2[e * HHv + k];
        }
#pragma unroll
        for (int e = 0; e < Ev; e++)
#pragma unroll
            for (int o = 16; o > 0; o >>= 1) ga[e] += __shfl_xor_sync(0xffffffffu, ga[e], o);
    }
    float g[Ev];
    if (lane == 0) {
        float m = -1e30f;
#pragma unroll
        for (int e = 0; e < Ev; e++) { g[e] = ga[e] + gb2[e]; m = fmaxf(m, g[e]); }
        float s = 0.f;
#pragma unroll
        for (int e = 0; e < Ev; e++) { g[e] = __expf(g[e] - m); s += g[e]; }
        float inv = 1.f / s;
#pragma unroll
        for (int e = 0; e < Ev; e++) {
            g[e] *= inv;
            gacc[b * Ev + e] += g[e];
        }
    }

    float tr0 = 0.f, tr1 = 0.f, dw = 0.f, wd = 0.f;
#pragma unroll
    for (int e = 0; e < Ev; e++) {
        float s0 = 0.f, s1 = 0.f, s2 = 0.f, s3 = 0.f;
        const float* ht = et + (size_t)b * H4 + e * HHv;
        const float* hi = ei + (size_t)b * H4 + e * HHv;
        const float* hw = ew + (size_t)b * H4 + e * HHv;
        const float* t0 = tW2 + (e * 2 + 0) * HHv;
        const float* t1 = tW2 + (e * 2 + 1) * HHv;
        const float* i0 = iW2 + e * HHv;
        const float* w0 = wW2 + e * HHv;
        for (int k = lane; k < HHv; k += 32) {
            float a = ht[k], bb = hi[k], c = hw[k];
            s0 += a * t0[k]; s1 += a * t1[k]; s2 += bb * i0[k]; s3 += c * w0[k];
        }
#pragma unroll
        for (int o = 16; o > 0; o >>= 1) {
            s0 += __shfl_xor_sync(0xffffffffu, s0, o);
            s1 += __shfl_xor_sync(0xffffffffu, s1, o);
            s2 += __shfl_xor_sync(0xffffffffu, s2, o);
            s3 += __shfl_xor_sync(0xffffffffu, s3, o);
        }
        if (lane == 0) {
            tr0 += g[e] * (s0 + tb2[e * 2 + 0]);
            tr1 += g[e] * (s1 + tb2[e * 2 + 1]);
            dw  += g[e] * (s2 + ib2[e]);
            wd  += g[e] * (s3 + wb2[e]);
        }
    }
    if (lane == 0) {
        out[(size_t)b * 16 + t]     = tr0;
        out[(size_t)b * 16 + 8 + t] = tr1;
        out[(size_t)Bv * 16 + (size_t)b * 8 + t] = dw;
        out[(size_t)Bv * 24 + (size_t)b * 8 + t] = wd;
        float* dn = din_next + b * 4;
        dn[0] = tr0; dn[1] = tr1; dn[2] = dw; dn[3] = wd;
    }
}

__global__ void fin_k(const float* __restrict__ gacc, float* __restrict__ out)
{
    int i = blockIdx.x * blockDim.x + threadIdx.x;
    if (i < Bv * Ev) out[(size_t)Bv * 32 + i] = gacc[i] * (1.f / HOR);
}

// ======================= launch =======================
extern "C" void kernel_launch(void* const* d_in, const int* in_sizes, int n_in,
                              void* d_out, int out_size)
{
    const float* x        = (const float*)d_in[0];
    const float* enc_Wih0 = (const float*)d_in[1];
    const float* enc_Whh0 = (const float*)d_in[2];
    const float* enc_b0   = (const float*)d_in[3];
    const float* enc_Wih1 = (const float*)d_in[4];
    const float* enc_Whh1 = (const float*)d_in[5];
    const float* enc_b1   = (const float*)d_in[6];
    const float* dec_Wih  = (const float*)d_in[7];
    const float* dec_Whh  = (const float*)d_in[8];
    const float* dec_b    = (const float*)d_in[9];
    const float* gW1      = (const float*)d_in[10];
    const float* gb1      = (const float*)d_in[11];
    const float* gW2      = (const float*)d_in[12];
    const float* gb2      = (const float*)d_in[13];
    const float* tW1      = (const float*)d_in[14];
    const float* tb1      = (const float*)d_in[15];
    const float* tW2      = (const float*)d_in[16];
    const float* tb2      = (const float*)d_in[17];
    const float* iW1      = (const float*)d_in[18];
    const float* ib1      = (const float*)d_in[19];
    const float* iW2      = (const float*)d_in[20];
    const float* ib2      = (const float*)d_in[21];
    const float* wW1      = (const float*)d_in[22];
    const float* wb1      = (const float*)d_in[23];
    const float* wW2      = (const float*)d_in[24];
    const float* wb2      = (const float*)d_in[25];
    float* out = (float*)d_out;

    cudaFuncSetAttribute(enc_fused, cudaFuncAttributeMaxDynamicSharedMemorySize, SM_BYTES);
    cudaFuncSetAttribute(dec_lstm,  cudaFuncAttributeMaxDynamicSharedMemorySize, SM_BYTES);
    cudaFuncSetAttribute(moe_gemm,  cudaFuncAttributeMaxDynamicSharedMemorySize, SM_BYTES);

    __half *h0t[2], *h1t[2];
    float *c0, *c1, *ghid, *et, *ei, *ew, *gacc, *din, *b0p, *b1p, *bdp, *Ws0, *Wsd;
    {
        void* p;
        cudaGetSymbolAddress(&p, g_h0t);  h0t[0] = (__half*)p; h0t[1] = h0t[0] + HT;
        cudaGetSymbolAddress(&p, g_h1t);  h1t[0] = (__half*)p; h1t[1] = h1t[0] + HT;
        cudaGetSymbolAddress(&p, g_c0);   c0 = (float*)p;
        cudaGetSymbolAddress(&p, g_c1);   c1 = (float*)p;
        cudaGetSymbolAddress(&p, g_ghid); ghid = (float*)p;
        cudaGetSymbolAddress(&p, g_et);   et = (float*)p;
        cudaGetSymbolAddress(&p, g_ei);   ei = (float*)p;
        cudaGetSymbolAddress(&p, g_ew);   ew = (float*)p;
        cudaGetSymbolAddress(&p, g_gacc); gacc = (float*)p;
        cudaGetSymbolAddress(&p, g_din);  din = (float*)p;
        cudaGetSymbolAddress(&p, g_b0p);  b0p = (float*)p;
        cudaGetSymbolAddress(&p, g_b1p);  b1p = (float*)p;
        cudaGetSymbolAddress(&p, g_bdp);  bdp = (float*)p;
        cudaGetSymbolAddress(&p, g_Ws0);  Ws0 = (float*)p;
        cudaGetSymbolAddress(&p, g_Wsd);  Wsd = (float*)p;
    }

    prep_all<<<1024, 256>>>(enc_Wih0, enc_Whh0, enc_b0, enc_Wih1, enc_Whh1, enc_b1,
                            dec_Wih, dec_Whh, dec_b, gW1, tW1, iW1, wW1);

    int p0 = 0, p1 = 0, pd = 0;

    // ---- encoder: skew-pipelined, 65 fused launches ----
    for (int t = 0; t <= Sv; t++) {
        int do0 = (t < Sv) ? 1 : 0;
        int do1 = (t > 0) ? 1 : 0;
        const float* xt = x + (do0 ? t : 0) * Fv;
        enc_fused<<<dim3(16, 16, 2), 256, SM_BYTES>>>(
            h0t[p0], b0p, xt, Ws0, c0, h0t[p0 ^ 1],
            h1t[p1], b1p, c1, h1t[p1 ^ 1], do0, do1);
        if (do0) p0 ^= 1;
        if (do1) p1 ^= 1;
    }

    // ---- decoder: 8 steps ----
    for (int t = 0; t < HOR; t++) {
        dec_lstm<<<dim3(16, 16), 256, SM_BYTES>>>(
            h1t[p1], bdp, din + pd * Bv * 4, Wsd, c1, h1t[p1 ^ 1]);
        p1 ^= 1;

        moe_gemm<<<dim3(50, 16), 256, SM_BYTES>>>(
            h1t[p1], gb1, ghid, tb1, et, ib1, ei, wb1, ew);

        head_comb<<<Bv / 8, 256>>>(ghid, gW2, gb2, et, ei, ew,
                                   tW2, tb2, iW2, ib2, wW2, wb2,
                                   gacc, out, din + (pd ^ 1) * Bv * 4, t);
        pd ^= 1;
    }

    fin_k<<<(Bv * Ev + 255) / 256, 256>>>(gacc, out);
}